// round 10
// baseline (speedup 1.0000x reference)
#include <cuda_runtime.h>
#include <cuda_bf16.h>
#include <cstdint>

// Problem constants
#define BNv 256
#define Dv  2048
#define Cv  256
#define Ev  128
#define Mv  4096
#define Vv  10

#define KEXT 144
#define ROWB (KEXT * 2)
#define SSTR 304

// Scratch
__device__ float g_xp[(size_t)Cv * BNv * Ev];
__device__ float g_esq[(size_t)Cv * Mv];
__device__ int   g_idx[(size_t)BNv * Cv];
__device__ int   g_cand[(size_t)BNv * Cv * 8];
__device__ __align__(16) unsigned char g_cbb[(size_t)Cv * Mv * ROWB];

// ---------------------------------------------------------------------------
__device__ __forceinline__ uint32_t smem_u32(const void* p) {
    uint32_t a;
    asm("{ .reg .u64 t; cvta.to.shared.u64 t, %1; cvt.u32.u64 %0, t; }" : "=r"(a) : "l"(p));
    return a;
}
__device__ __forceinline__ void cp16(uint32_t dst, const void* src) {
    asm volatile("cp.async.cg.shared.global [%0], [%1], 16;" :: "r"(dst), "l"(src) : "memory");
}
__device__ __forceinline__ void cp_commit() { asm volatile("cp.async.commit_group;" ::: "memory"); }
__device__ __forceinline__ void cp_wait0()  { asm volatile("cp.async.wait_group 0;"  ::: "memory"); }

__device__ __forceinline__ void ldm4(uint32_t& r0, uint32_t& r1, uint32_t& r2, uint32_t& r3, uint32_t a) {
    asm volatile("ldmatrix.sync.aligned.m8n8.x4.shared.b16 {%0,%1,%2,%3}, [%4];"
                 : "=r"(r0), "=r"(r1), "=r"(r2), "=r"(r3) : "r"(a));
}
__device__ __forceinline__ void mma16816(float* c, const uint32_t* a, uint32_t b0, uint32_t b1) {
    asm volatile("mma.sync.aligned.m16n8k16.row.col.f32.bf16.bf16.f32 "
                 "{%0,%1,%2,%3}, {%4,%5,%6,%7}, {%8,%9}, {%0,%1,%2,%3};"
                 : "+f"(c[0]), "+f"(c[1]), "+f"(c[2]), "+f"(c[3])
                 : "r"(a[0]), "r"(a[1]), "r"(a[2]), "r"(a[3]), "r"(b0), "r"(b1));
}
__device__ __forceinline__ uint32_t pack_bf2(float x, float y) {
    return ((uint32_t)__bfloat16_as_ushort(__float2bfloat16(y)) << 16) |
           __bfloat16_as_ushort(__float2bfloat16(x));
}
// packed fp32x2 helpers (Blackwell FFMA2) -- each lane is an exact fp32 RN fma
__device__ __forceinline__ void unpack_ff(unsigned long long d, float& x, float& y) {
    asm("mov.b64 {%0, %1}, %2;" : "=f"(x), "=f"(y) : "l"(d));
}
__device__ __forceinline__ void ffma2(unsigned long long& d, unsigned long long a, unsigned long long b) {
    asm("fma.rn.f32x2 %0, %1, %2, %0;" : "+l"(d) : "l"(a), "l"(b));
}

// ---------------------------------------------------------------------------
// stage1 (fused with prep): xp = emb . rp via packed FFMA2, PLUS codebook
// conversion (g_cbb bf16 ext rows + g_esq), interleaved as 16-row bursts.
// Numerics: xp per element = sequential-k fp32 fma chain (bitwise = R1/R9);
// esq/cbb code verbatim from the passing prep kernel.
// grid 512 = (c = bx>>1, bn-half = bx&1). 256 thr / 8 warps.
// Block GEMM tile 128bn x 128e; thread 8bn x 8e as 4 bn-pairs x 8 e.
// Prep: block bx owns cb rows [bx*2048, bx*2048+2048); warp w rows
// [base + w*256 .. +256) in 16-row bursts every 8 k-chunks.
// ---------------------------------------------------------------------------
__global__ void __launch_bounds__(256, 2) stage1_kernel(const float* __restrict__ emb,
                                                        const float* __restrict__ rp,
                                                        const float* __restrict__ cb) {
    __shared__ __align__(16) float As[16][130];                  // [k][bn]
    __shared__ __align__(16) unsigned long long Bsd[16][132];    // [k][e] dup pairs

    const int t = threadIdx.x;
    const int c = blockIdx.x >> 1;
    const int bn0g = (blockIdx.x & 1) * 128;
    const float* __restrict__ bb = rp + (size_t)c * (Dv * Ev);

    const int wid  = t >> 5, lane = t & 31;
    const int wbn  = wid & 3;
    const int we   = wid >> 2;
    const int g    = lane >> 3;
    const int el   = lane & 7;

    // GEMM LDG mappings
    const int arow = t >> 1;
    const int akq  = (t & 1) * 8;
    const int bk   = t >> 4;
    const int be   = (t & 15) * 8;

    const float* __restrict__ aptr = emb + (size_t)(bn0g + arow) * Dv + akq;
    const float* __restrict__ bptr = bb + (size_t)bk * Ev + be;

    // prep row base for this warp
    const size_t prow_base = (size_t)blockIdx.x * 2048 + (size_t)wid * 256;

    float4 av0 = *(const float4*)(aptr);
    float4 av1 = *(const float4*)(aptr + 4);
    float4 bv0 = *(const float4*)(bptr);
    float4 bv1 = *(const float4*)(bptr + 4);

    unsigned long long acc2[4][8];
    #pragma unroll
    for (int p = 0; p < 4; p++)
        #pragma unroll
        for (int j = 0; j < 8; j++) acc2[p][j] = 0ull;

    const int abase = wbn * 32 + g * 8;
    const int ebase = we * 64 + el;

    for (int chunk = 0; chunk < 128; chunk++) {
        __syncthreads();   // previous tile fully consumed
        As[akq + 0][arow] = av0.x;
        As[akq + 1][arow] = av0.y;
        As[akq + 2][arow] = av0.z;
        As[akq + 3][arow] = av0.w;
        As[akq + 4][arow] = av1.x;
        As[akq + 5][arow] = av1.y;
        As[akq + 6][arow] = av1.z;
        As[akq + 7][arow] = av1.w;
        {
            uint4 w0 = make_uint4(__float_as_uint(bv0.x), __float_as_uint(bv0.x),
                                  __float_as_uint(bv0.y), __float_as_uint(bv0.y));
            uint4 w1 = make_uint4(__float_as_uint(bv0.z), __float_as_uint(bv0.z),
                                  __float_as_uint(bv0.w), __float_as_uint(bv0.w));
            uint4 w2 = make_uint4(__float_as_uint(bv1.x), __float_as_uint(bv1.x),
                                  __float_as_uint(bv1.y), __float_as_uint(bv1.y));
            uint4 w3 = make_uint4(__float_as_uint(bv1.z), __float_as_uint(bv1.z),
                                  __float_as_uint(bv1.w), __float_as_uint(bv1.w));
            *(uint4*)&Bsd[bk][be + 0] = w0;
            *(uint4*)&Bsd[bk][be + 2] = w1;
            *(uint4*)&Bsd[bk][be + 4] = w2;
            *(uint4*)&Bsd[bk][be + 6] = w3;
        }
        __syncthreads();

        const int k0 = chunk * 16;
        if (k0 + 16 < Dv) {
            av0 = *(const float4*)(aptr + (k0 + 16));
            av1 = *(const float4*)(aptr + (k0 + 16) + 4);
            bv0 = *(const float4*)(bptr + (size_t)(k0 + 16) * Ev);
            bv1 = *(const float4*)(bptr + (size_t)(k0 + 16) * Ev + 4);
        }

        // ---- prep burst: every 8 chunks, convert 16 codebook rows per warp
        if ((chunk & 7) == 0) {
            const size_t r00 = prow_base + (size_t)(chunk >> 3) * 16;
            #pragma unroll
            for (int g4 = 0; g4 < 4; g4++) {
                float4 pv[4];
                const size_t r0 = r00 + g4 * 4;
                #pragma unroll
                for (int i = 0; i < 4; i++)
                    pv[i] = *(const float4*)(cb + (r0 + i) * Ev + lane * 4);
                #pragma unroll
                for (int i = 0; i < 4; i++) {
                    const size_t row = r0 + i;
                    float4 v = pv[i];
                    float s = v.x * v.x + v.y * v.y + v.z * v.z + v.w * v.w;
                    #pragma unroll
                    for (int o = 16; o; o >>= 1) s += __shfl_xor_sync(0xffffffffu, s, o);
                    unsigned char* dst = g_cbb + row * ROWB;
                    uint2 u;
                    u.x = pack_bf2(v.x, v.y);
                    u.y = pack_bf2(v.z, v.w);
                    *(uint2*)(dst + lane * 8) = u;
                    if (lane == 0) {
                        g_esq[row] = s;
                        __nv_bfloat16 hi = __float2bfloat16(s);
                        float lo = s - __bfloat162float(hi);
                        *(uint32_t*)(dst + 256) =
                            ((uint32_t)__bfloat16_as_ushort(__float2bfloat16(lo)) << 16) |
                            __bfloat16_as_ushort(hi);
                    } else if (lane < 8) {
                        *(uint32_t*)(dst + 256 + lane * 4) = 0u;
                    }
                }
            }
        }

        #pragma unroll
        for (int kk = 0; kk < 16; kk++) {
            unsigned long long a2[4], b2[8];
            #pragma unroll
            for (int p = 0; p < 4; p++)
                a2[p] = *(const unsigned long long*)&As[kk][abase + 2 * p];
            #pragma unroll
            for (int j = 0; j < 8; j++)
                b2[j] = Bsd[kk][ebase + 8 * j];
            #pragma unroll
            for (int p = 0; p < 4; p++)
                #pragma unroll
                for (int j = 0; j < 8; j++)
                    ffma2(acc2[p][j], a2[p], b2[j]);
        }
    }

    // store xp: pair (bn, bn+1) same e
    #pragma unroll
    for (int p = 0; p < 4; p++) {
        const int bn = bn0g + abase + 2 * p;
        #pragma unroll
        for (int j = 0; j < 8; j++) {
            float v0, v1;
            unpack_ff(acc2[p][j], v0, v1);
            const size_t base = ((size_t)c * BNv + bn) * Ev + ebase + 8 * j;
            g_xp[base]      = v0;
            g_xp[base + Ev] = v1;
        }
    }
}

// ---------------------------------------------------------------------------
// mma stage (stage2): bf16 candidates, unchanged (passed R3/R9)
// ---------------------------------------------------------------------------
#define XS_BYTES (256 * SSTR)
#define CB_BYTES (64 * SSTR)
#define SMEM2 (XS_BYTES + 2 * CB_BYTES)

__global__ void __launch_bounds__(256, 1) mma_kernel() {
    extern __shared__ __align__(16) unsigned char sm[];
    const uint32_t smb = smem_u32(sm);
    const int tid  = threadIdx.x;
    const int w    = tid >> 5;
    const int lane = tid & 31;
    const int c  = blockIdx.x >> 1;
    const int mh = blockIdx.x & 1;

    {
        const int r = tid;
        const float* xr = g_xp + ((size_t)c * BNv + r) * Ev;
        unsigned char* xd = sm + (size_t)r * SSTR;
        #pragma unroll 8
        for (int q = 0; q < 32; q++) {
            float4 v = *(const float4*)(xr + q * 4);
            uint2 u;
            u.x = pack_bf2(-2.f * v.x, -2.f * v.y);
            u.y = pack_bf2(-2.f * v.z, -2.f * v.w);
            *(uint2*)(xd + q * 8) = u;
        }
        *(uint32_t*)(xd + 256) = 0x3F803F80u;
        #pragma unroll
        for (int t = 0; t < 7; t++) *(uint32_t*)(xd + 260 + t * 4) = 0u;
    }

    const size_t cb_base = (size_t)(c * Mv + mh * 2048) * ROWB;
    const uint32_t cbs = smb + XS_BYTES;
    {
        #pragma unroll
        for (int s = 0; s < 5; s++) {
            int idx = tid + s * 256;
            if (idx < 1152) {
                int row = idx / 18, ch = idx % 18;
                cp16(cbs + row * SSTR + ch * 16, g_cbb + cb_base + (size_t)row * ROWB + ch * 16);
            }
        }
        cp_commit();
    }

    const int grp = lane >> 3;
    const uint32_t a_off = ((grp & 1) * 8 + (lane & 7)) * SSTR + (grp >> 1) * 16;
    const uint32_t b_off = ((grp >> 1) * 8 + (lane & 7)) * SSTR + (grp & 1) * 16;
    const uint32_t xw = smb + (w * 32) * SSTR + a_off;

    float ts[4][3];
    int   tm[4][3];
    #pragma unroll
    for (int r = 0; r < 4; r++)
        #pragma unroll
        for (int e = 0; e < 3; e++) { ts[r][e] = 3.4e38f; tm[r][e] = 0; }

    for (int it = 0; it < 32; it++) {
        const int buf = it & 1;
        cp_wait0();
        __syncthreads();
        if (it < 31) {
            const uint32_t dst = cbs + (buf ^ 1) * CB_BYTES;
            const size_t src = cb_base + (size_t)(it + 1) * 64 * ROWB;
            #pragma unroll
            for (int s = 0; s < 5; s++) {
                int idx = tid + s * 256;
                if (idx < 1152) {
                    int row = idx / 18, ch = idx % 18;
                    cp16(dst + row * SSTR + ch * 16, g_cbb + src + (size_t)row * ROWB + ch * 16);
                }
            }
            cp_commit();
        }

        float acc[2][8][4];
        #pragma unroll
        for (int i = 0; i < 2; i++)
            #pragma unroll
            for (int j = 0; j < 8; j++)
                #pragma unroll
                for (int e = 0; e < 4; e++) acc[i][j][e] = 0.f;

        const uint32_t cw = cbs + buf * CB_BYTES + b_off;

        #pragma unroll
        for (int ks = 0; ks < 9; ks++) {
            uint32_t A[2][4], B[8][2];
            #pragma unroll
            for (int i = 0; i < 2; i++)
                ldm4(A[i][0], A[i][1], A[i][2], A[i][3], xw + i * 16 * SSTR + ks * 32);
            #pragma unroll
            for (int jj = 0; jj < 4; jj++) {
                uint32_t r0, r1, r2, r3;
                ldm4(r0, r1, r2, r3, cw + jj * 16 * SSTR + ks * 32);
                B[2 * jj][0] = r0; B[2 * jj][1] = r1;
                B[2 * jj + 1][0] = r2; B[2 * jj + 1][1] = r3;
            }
            #pragma unroll
            for (int i = 0; i < 2; i++)
                #pragma unroll
                for (int j = 0; j < 8; j++)
                    mma16816(acc[i][j], A[i], B[j][0], B[j][1]);
        }

        const int mb = it * 64 + (lane & 3) * 2;
        #pragma unroll
        for (int i = 0; i < 2; i++)
            #pragma unroll
            for (int j = 0; j < 8; j++) {
                const int m0 = mb + j * 8;
                #pragma unroll
                for (int half = 0; half < 2; half++) {
                    const int rs = i * 2 + half;
                    #pragma unroll
                    for (int e = 0; e < 2; e++) {
                        float v = acc[i][j][half * 2 + e];
                        int   m = m0 + e;
                        if (v < ts[rs][2]) {
                            if (v < ts[rs][1]) {
                                if (v < ts[rs][0]) {
                                    ts[rs][2]=ts[rs][1]; tm[rs][2]=tm[rs][1];
                                    ts[rs][1]=ts[rs][0]; tm[rs][1]=tm[rs][0];
                                    ts[rs][0]=v; tm[rs][0]=m;
                                } else {
                                    ts[rs][2]=ts[rs][1]; tm[rs][2]=tm[rs][1];
                                    ts[rs][1]=v; tm[rs][1]=m;
                                }
                            } else { ts[rs][2]=v; tm[rs][2]=m; }
                        }
                    }
                }
            }
        __syncthreads();
    }

    const uint32_t FULL = 0xffffffffu;
    #pragma unroll
    for (int rs = 0; rs < 4; rs++) {
        float m4s[4] = {3.4e38f, 3.4e38f, 3.4e38f, 3.4e38f};
        int   m4i[4] = {0, 0, 0, 0};
        #pragma unroll
        for (int src = 0; src < 4; src++) {
            #pragma unroll
            for (int e = 0; e < 3; e++) {
                float vs = __shfl_sync(FULL, ts[rs][e], (lane & ~3) + src);
                int   vm = __shfl_sync(FULL, tm[rs][e], (lane & ~3) + src);
                if ((lane & 3) == 0) {
                    if (vs < m4s[3]) {
                        if (vs < m4s[1]) {
                            if (vs < m4s[0]) {
                                m4s[3]=m4s[2]; m4i[3]=m4i[2]; m4s[2]=m4s[1]; m4i[2]=m4i[1];
                                m4s[1]=m4s[0]; m4i[1]=m4i[0]; m4s[0]=vs; m4i[0]=vm;
                            } else {
                                m4s[3]=m4s[2]; m4i[3]=m4i[2]; m4s[2]=m4s[1]; m4i[2]=m4i[1];
                                m4s[1]=vs; m4i[1]=vm;
                            }
                        } else {
                            if (vs < m4s[2]) { m4s[3]=m4s[2]; m4i[3]=m4i[2]; m4s[2]=vs; m4i[2]=vm; }
                            else             { m4s[3]=vs; m4i[3]=vm; }
                        }
                    }
                }
            }
        }
        if ((lane & 3) == 0) {
            int bn = w * 32 + (rs >> 1) * 16 + (lane >> 2) + (rs & 1) * 8;
            size_t base = ((size_t)bn * Cv + c) * 8 + mh * 4;
            #pragma unroll
            for (int t = 0; t < 4; t++) g_cand[base + t] = mh * 2048 + m4i[t];
        }
    }
}

// ---------------------------------------------------------------------------
__global__ void __launch_bounds__(256) rescore_kernel(const float* __restrict__ cb) {
    int wp   = (blockIdx.x * 256 + threadIdx.x) >> 5;
    int lane = threadIdx.x & 31;
    int bn   = wp >> 8;
    int c    = wp & 255;
    float4 x = *(const float4*)(g_xp + ((size_t)c * BNv + bn) * Ev + lane * 4);
    float best = 3.4e38f; int bm = Mv;
    #pragma unroll
    for (int t = 0; t < 8; t++) {
        int m = g_cand[((size_t)bn * Cv + c) * 8 + t];
        float4 cv = *(const float4*)(cb + ((size_t)c * Mv + m) * Ev + lane * 4);
        float d = x.x * cv.x + x.y * cv.y + x.z * cv.z + x.w * cv.w;
        #pragma unroll
        for (int o = 16; o; o >>= 1) d += __shfl_xor_sync(0xffffffffu, d, o);
        float s = g_esq[(size_t)c * Mv + m] - 2.f * d;
        if (s < best || (s == best && m < bm)) { best = s; bm = m; }
    }
    if (lane == 0) g_idx[(size_t)bn * Cv + c] = bm;
}

// ---------------------------------------------------------------------------
__global__ void __launch_bounds__(256) stage3_kernel(const float* __restrict__ vals,
                                                     float* __restrict__ out) {
    __shared__ float sh[256][Vv];
    const int bn = blockIdx.x;
    const int c  = threadIdx.x;
    int m = g_idx[(size_t)bn * Cv + c];
    const float* vp = vals + ((size_t)c * Mv + m) * Vv;
    #pragma unroll
    for (int v = 0; v < Vv; v++) sh[c][v] = vp[v];
    __syncthreads();
    if (c < Vv) {
        float s = 0.f;
        for (int k = 0; k < 256; k++) s += sh[k][c];
        out[(size_t)bn * Vv + c] = s * (1.f / 256.f);
    }
}

// ---------------------------------------------------------------------------
extern "C" void kernel_launch(void* const* d_in, const int* in_sizes, int n_in,
                              void* d_out, int out_size) {
    const float* emb  = (const float*)d_in[0];
    const float* rp   = (const float*)d_in[1];
    const float* cb   = (const float*)d_in[2];
    const float* vals = (const float*)d_in[3];
    float* out = (float*)d_out;

    cudaFuncSetAttribute(mma_kernel, cudaFuncAttributeMaxDynamicSharedMemorySize, SMEM2);

    stage1_kernel<<<Cv * 2, 256>>>(emb, rp, cb);
    mma_kernel<<<Cv * 2, 256, SMEM2>>>();
    rescore_kernel<<<(BNv * Cv) / 8, 256>>>(cb);
    stage3_kernel<<<BNv, 256>>>(vals, out);
}

// round 11
// speedup vs baseline: 1.0849x; 1.0849x over previous
#include <cuda_runtime.h>
#include <cuda_bf16.h>
#include <cstdint>

// Problem constants
#define BNv 256
#define Dv  2048
#define Cv  256
#define Ev  128
#define Mv  4096
#define Vv  10

#define KEXT 144
#define ROWB (KEXT * 2)
#define SSTR 304

// Scratch
__device__ float g_xp[(size_t)Cv * BNv * Ev];
__device__ float g_esq[(size_t)Cv * Mv];
__device__ int   g_idx[(size_t)BNv * Cv];
__device__ int   g_cand[(size_t)BNv * Cv * 8];
__device__ __align__(16) unsigned char g_cbb[(size_t)Cv * Mv * ROWB];

// ---------------------------------------------------------------------------
__device__ __forceinline__ uint32_t smem_u32(const void* p) {
    uint32_t a;
    asm("{ .reg .u64 t; cvta.to.shared.u64 t, %1; cvt.u32.u64 %0, t; }" : "=r"(a) : "l"(p));
    return a;
}
__device__ __forceinline__ void cp16(uint32_t dst, const void* src) {
    asm volatile("cp.async.cg.shared.global [%0], [%1], 16;" :: "r"(dst), "l"(src) : "memory");
}
__device__ __forceinline__ void cp_commit() { asm volatile("cp.async.commit_group;" ::: "memory"); }
__device__ __forceinline__ void cp_wait0()  { asm volatile("cp.async.wait_group 0;"  ::: "memory"); }

__device__ __forceinline__ void ldm4(uint32_t& r0, uint32_t& r1, uint32_t& r2, uint32_t& r3, uint32_t a) {
    asm volatile("ldmatrix.sync.aligned.m8n8.x4.shared.b16 {%0,%1,%2,%3}, [%4];"
                 : "=r"(r0), "=r"(r1), "=r"(r2), "=r"(r3) : "r"(a));
}
__device__ __forceinline__ void mma16816(float* c, const uint32_t* a, uint32_t b0, uint32_t b1) {
    asm volatile("mma.sync.aligned.m16n8k16.row.col.f32.bf16.bf16.f32 "
                 "{%0,%1,%2,%3}, {%4,%5,%6,%7}, {%8,%9}, {%0,%1,%2,%3};"
                 : "+f"(c[0]), "+f"(c[1]), "+f"(c[2]), "+f"(c[3])
                 : "r"(a[0]), "r"(a[1]), "r"(a[2]), "r"(a[3]), "r"(b0), "r"(b1));
}
__device__ __forceinline__ uint32_t pack_bf2(float x, float y) {
    return ((uint32_t)__bfloat16_as_ushort(__float2bfloat16(y)) << 16) |
           __bfloat16_as_ushort(__float2bfloat16(x));
}
// packed fp32x2 helpers (Blackwell FFMA2) -- each lane is an exact fp32 RN fma
__device__ __forceinline__ void unpack_ff(unsigned long long d, float& x, float& y) {
    asm("mov.b64 {%0, %1}, %2;" : "=f"(x), "=f"(y) : "l"(d));
}
__device__ __forceinline__ void ffma2(unsigned long long& d, unsigned long long a, unsigned long long b) {
    asm("fma.rn.f32x2 %0, %1, %2, %0;" : "+l"(d) : "l"(a), "l"(b));
}

// ---------------------------------------------------------------------------
// prep: codebook -> bf16 ext rows [cb | esq_hi | esq_lo | zeros], + g_esq
// (separate kernel again -- fusing into stage1 spilled registers, R10)
// ---------------------------------------------------------------------------
__global__ void __launch_bounds__(256) prep_kernel(const float* __restrict__ cb) {
    int row  = (blockIdx.x * 256 + threadIdx.x) >> 5;
    int lane = threadIdx.x & 31;
    float4 v = *(const float4*)(cb + (size_t)row * Ev + lane * 4);
    float s = v.x * v.x + v.y * v.y + v.z * v.z + v.w * v.w;
    #pragma unroll
    for (int o = 16; o; o >>= 1) s += __shfl_xor_sync(0xffffffffu, s, o);

    unsigned char* dst = g_cbb + (size_t)row * ROWB;
    uint2 u;
    u.x = pack_bf2(v.x, v.y);
    u.y = pack_bf2(v.z, v.w);
    *(uint2*)(dst + lane * 8) = u;

    if (lane == 0) {
        g_esq[row] = s;
        __nv_bfloat16 hi = __float2bfloat16(s);
        float lo = s - __bfloat162float(hi);
        *(uint32_t*)(dst + 256) =
            ((uint32_t)__bfloat16_as_ushort(__float2bfloat16(lo)) << 16) |
            __bfloat16_as_ushort(hi);
    } else if (lane < 8) {
        *(uint32_t*)(dst + 256 + lane * 4) = 0u;
    }
}

// ---------------------------------------------------------------------------
// stage1: xp = emb . rp via packed FFMA2.
// Numerics: per element acc = fma(a_k,b_k,acc), k ascending -> bitwise = R9.
// grid 512 = (c, bn-half). 256 thr / 8 warps. Block tile 128bn x 128e.
// Thread tile: 4 bn-pairs x 8 consecutive e.
// smem double-buffered: As [16][132] f32 (A transposed), Bsd [16][132] u64
// ({b,b} dup pairs, XOR-swizzled slots for conflict-free LDS.128).
// ---------------------------------------------------------------------------
#define S1_AS 8448                       // 16*132*4
#define S1_BS 16896                      // 16*132*8
#define S1_SMEM (2 * (S1_AS + S1_BS))    // 50688

__device__ __forceinline__ int bsw(int s) { return s ^ (((s >> 4) & 3) << 1); }

__global__ void __launch_bounds__(256, 2) stage1_kernel(const float* __restrict__ emb,
                                                        const float* __restrict__ rp) {
    extern __shared__ __align__(16) unsigned char s1[];
    const int t = threadIdx.x;
    const int c = blockIdx.x >> 1;
    const int bn0g = (blockIdx.x & 1) * 128;
    const float* __restrict__ bb = rp + (size_t)c * (Dv * Ev);

    const int wid = t >> 5, lane = t & 31;
    const int wbn = wid & 3;            // bn warp block *32
    const int we  = wid >> 2;           // e warp block *64
    const int g   = lane >> 3;          // bn subgroup *8
    const int el  = lane & 7;           // e subgroup *8

    // LDG mappings
    const int arow = t >> 1;            // 0..127
    const int akq  = (t & 1) * 8;       // k offset 0/8
    const int bk   = t >> 4;            // 0..15
    const int bes  = (t & 15) * 8;      // e slot base

    const float* __restrict__ aptr = emb + (size_t)(bn0g + arow) * Dv + akq;
    const float* __restrict__ bptr = bb + (size_t)bk * Ev + bes;

    float4 av0 = *(const float4*)(aptr);
    float4 av1 = *(const float4*)(aptr + 4);
    float4 bv0 = *(const float4*)(bptr);
    float4 bv1 = *(const float4*)(bptr + 4);

    unsigned long long acc2[4][8];
    #pragma unroll
    for (int p = 0; p < 4; p++)
        #pragma unroll
        for (int j = 0; j < 8; j++) acc2[p][j] = 0ull;

    const int abase = wbn * 32 + g * 8;
    // swizzled B slots
    int wslot0 = bsw(bes + 0), wslot1 = bsw(bes + 2), wslot2 = bsw(bes + 4), wslot3 = bsw(bes + 6);
    const int ebs = we * 64 + el * 8;
    int rslot0 = bsw(ebs + 0), rslot1 = bsw(ebs + 2), rslot2 = bsw(ebs + 4), rslot3 = bsw(ebs + 6);

    for (int chunk = 0; chunk < 128; chunk++) {
        float* As = (float*)(s1 + (chunk & 1) * S1_AS);
        unsigned long long* Bsd = (unsigned long long*)(s1 + 2 * S1_AS + (chunk & 1) * S1_BS);

        As[(akq + 0) * 132 + arow] = av0.x;
        As[(akq + 1) * 132 + arow] = av0.y;
        As[(akq + 2) * 132 + arow] = av0.z;
        As[(akq + 3) * 132 + arow] = av0.w;
        As[(akq + 4) * 132 + arow] = av1.x;
        As[(akq + 5) * 132 + arow] = av1.y;
        As[(akq + 6) * 132 + arow] = av1.z;
        As[(akq + 7) * 132 + arow] = av1.w;
        {
            uint4 w0 = make_uint4(__float_as_uint(bv0.x), __float_as_uint(bv0.x),
                                  __float_as_uint(bv0.y), __float_as_uint(bv0.y));
            uint4 w1 = make_uint4(__float_as_uint(bv0.z), __float_as_uint(bv0.z),
                                  __float_as_uint(bv0.w), __float_as_uint(bv0.w));
            uint4 w2 = make_uint4(__float_as_uint(bv1.x), __float_as_uint(bv1.x),
                                  __float_as_uint(bv1.y), __float_as_uint(bv1.y));
            uint4 w3 = make_uint4(__float_as_uint(bv1.z), __float_as_uint(bv1.z),
                                  __float_as_uint(bv1.w), __float_as_uint(bv1.w));
            *(uint4*)&Bsd[bk * 132 + wslot0] = w0;
            *(uint4*)&Bsd[bk * 132 + wslot1] = w1;
            *(uint4*)&Bsd[bk * 132 + wslot2] = w2;
            *(uint4*)&Bsd[bk * 132 + wslot3] = w3;
        }
        __syncthreads();

        const int k0 = chunk * 16;
        if (k0 + 16 < Dv) {
            av0 = *(const float4*)(aptr + (k0 + 16));
            av1 = *(const float4*)(aptr + (k0 + 16) + 4);
            bv0 = *(const float4*)(bptr + (size_t)(k0 + 16) * Ev);
            bv1 = *(const float4*)(bptr + (size_t)(k0 + 16) * Ev + 4);
        }

        #pragma unroll
        for (int kk = 0; kk < 16; kk++) {
            unsigned long long a2[4], b2[8];
            *(uint4*)&a2[0] = *(const uint4*)&As[kk * 132 + abase];
            *(uint4*)&a2[2] = *(const uint4*)&As[kk * 132 + abase + 4];
            *(uint4*)&b2[0] = *(const uint4*)&Bsd[kk * 132 + rslot0];
            *(uint4*)&b2[2] = *(const uint4*)&Bsd[kk * 132 + rslot1];
            *(uint4*)&b2[4] = *(const uint4*)&Bsd[kk * 132 + rslot2];
            *(uint4*)&b2[6] = *(const uint4*)&Bsd[kk * 132 + rslot3];
            #pragma unroll
            for (int p = 0; p < 4; p++)
                #pragma unroll
                for (int j = 0; j < 8; j++)
                    ffma2(acc2[p][j], a2[p], b2[j]);
        }
    }

    // store xp: thread owns bn pairs (abase+2p, +1) x e [ebs, ebs+8)
    #pragma unroll
    for (int p = 0; p < 4; p++) {
        float lo[8], hi[8];
        #pragma unroll
        for (int j = 0; j < 8; j++) unpack_ff(acc2[p][j], lo[j], hi[j]);
        const size_t base = ((size_t)c * BNv + bn0g + abase + 2 * p) * Ev + ebs;
        *(float4*)(g_xp + base)          = make_float4(lo[0], lo[1], lo[2], lo[3]);
        *(float4*)(g_xp + base + 4)      = make_float4(lo[4], lo[5], lo[6], lo[7]);
        *(float4*)(g_xp + base + Ev)     = make_float4(hi[0], hi[1], hi[2], hi[3]);
        *(float4*)(g_xp + base + Ev + 4) = make_float4(hi[4], hi[5], hi[6], hi[7]);
    }
}

// ---------------------------------------------------------------------------
// mma stage (stage2): bf16 candidates, unchanged (passed R3/R9)
// ---------------------------------------------------------------------------
#define XS_BYTES (256 * SSTR)
#define CB_BYTES (64 * SSTR)
#define SMEM2 (XS_BYTES + 2 * CB_BYTES)

__global__ void __launch_bounds__(256, 1) mma_kernel() {
    extern __shared__ __align__(16) unsigned char sm[];
    const uint32_t smb = smem_u32(sm);
    const int tid  = threadIdx.x;
    const int w    = tid >> 5;
    const int lane = tid & 31;
    const int c  = blockIdx.x >> 1;
    const int mh = blockIdx.x & 1;

    {
        const int r = tid;
        const float* xr = g_xp + ((size_t)c * BNv + r) * Ev;
        unsigned char* xd = sm + (size_t)r * SSTR;
        #pragma unroll 8
        for (int q = 0; q < 32; q++) {
            float4 v = *(const float4*)(xr + q * 4);
            uint2 u;
            u.x = pack_bf2(-2.f * v.x, -2.f * v.y);
            u.y = pack_bf2(-2.f * v.z, -2.f * v.w);
            *(uint2*)(xd + q * 8) = u;
        }
        *(uint32_t*)(xd + 256) = 0x3F803F80u;
        #pragma unroll
        for (int t = 0; t < 7; t++) *(uint32_t*)(xd + 260 + t * 4) = 0u;
    }

    const size_t cb_base = (size_t)(c * Mv + mh * 2048) * ROWB;
    const uint32_t cbs = smb + XS_BYTES;
    {
        #pragma unroll
        for (int s = 0; s < 5; s++) {
            int idx = tid + s * 256;
            if (idx < 1152) {
                int row = idx / 18, ch = idx % 18;
                cp16(cbs + row * SSTR + ch * 16, g_cbb + cb_base + (size_t)row * ROWB + ch * 16);
            }
        }
        cp_commit();
    }

    const int grp = lane >> 3;
    const uint32_t a_off = ((grp & 1) * 8 + (lane & 7)) * SSTR + (grp >> 1) * 16;
    const uint32_t b_off = ((grp >> 1) * 8 + (lane & 7)) * SSTR + (grp & 1) * 16;
    const uint32_t xw = smb + (w * 32) * SSTR + a_off;

    float ts[4][3];
    int   tm[4][3];
    #pragma unroll
    for (int r = 0; r < 4; r++)
        #pragma unroll
        for (int e = 0; e < 3; e++) { ts[r][e] = 3.4e38f; tm[r][e] = 0; }

    for (int it = 0; it < 32; it++) {
        const int buf = it & 1;
        cp_wait0();
        __syncthreads();
        if (it < 31) {
            const uint32_t dst = cbs + (buf ^ 1) * CB_BYTES;
            const size_t src = cb_base + (size_t)(it + 1) * 64 * ROWB;
            #pragma unroll
            for (int s = 0; s < 5; s++) {
                int idx = tid + s * 256;
                if (idx < 1152) {
                    int row = idx / 18, ch = idx % 18;
                    cp16(dst + row * SSTR + ch * 16, g_cbb + src + (size_t)row * ROWB + ch * 16);
                }
            }
            cp_commit();
        }

        float acc[2][8][4];
        #pragma unroll
        for (int i = 0; i < 2; i++)
            #pragma unroll
            for (int j = 0; j < 8; j++)
                #pragma unroll
                for (int e = 0; e < 4; e++) acc[i][j][e] = 0.f;

        const uint32_t cw = cbs + buf * CB_BYTES + b_off;

        #pragma unroll
        for (int ks = 0; ks < 9; ks++) {
            uint32_t A[2][4], B[8][2];
            #pragma unroll
            for (int i = 0; i < 2; i++)
                ldm4(A[i][0], A[i][1], A[i][2], A[i][3], xw + i * 16 * SSTR + ks * 32);
            #pragma unroll
            for (int jj = 0; jj < 4; jj++) {
                uint32_t r0, r1, r2, r3;
                ldm4(r0, r1, r2, r3, cw + jj * 16 * SSTR + ks * 32);
                B[2 * jj][0] = r0; B[2 * jj][1] = r1;
                B[2 * jj + 1][0] = r2; B[2 * jj + 1][1] = r3;
            }
            #pragma unroll
            for (int i = 0; i < 2; i++)
                #pragma unroll
                for (int j = 0; j < 8; j++)
                    mma16816(acc[i][j], A[i], B[j][0], B[j][1]);
        }

        const int mb = it * 64 + (lane & 3) * 2;
        #pragma unroll
        for (int i = 0; i < 2; i++)
            #pragma unroll
            for (int j = 0; j < 8; j++) {
                const int m0 = mb + j * 8;
                #pragma unroll
                for (int half = 0; half < 2; half++) {
                    const int rs = i * 2 + half;
                    #pragma unroll
                    for (int e = 0; e < 2; e++) {
                        float v = acc[i][j][half * 2 + e];
                        int   m = m0 + e;
                        if (v < ts[rs][2]) {
                            if (v < ts[rs][1]) {
                                if (v < ts[rs][0]) {
                                    ts[rs][2]=ts[rs][1]; tm[rs][2]=tm[rs][1];
                                    ts[rs][1]=ts[rs][0]; tm[rs][1]=tm[rs][0];
                                    ts[rs][0]=v; tm[rs][0]=m;
                                } else {
                                    ts[rs][2]=ts[rs][1]; tm[rs][2]=tm[rs][1];
                                    ts[rs][1]=v; tm[rs][1]=m;
                                }
                            } else { ts[rs][2]=v; tm[rs][2]=m; }
                        }
                    }
                }
            }
        __syncthreads();
    }

    const uint32_t FULL = 0xffffffffu;
    #pragma unroll
    for (int rs = 0; rs < 4; rs++) {
        float m4s[4] = {3.4e38f, 3.4e38f, 3.4e38f, 3.4e38f};
        int   m4i[4] = {0, 0, 0, 0};
        #pragma unroll
        for (int src = 0; src < 4; src++) {
            #pragma unroll
            for (int e = 0; e < 3; e++) {
                float vs = __shfl_sync(FULL, ts[rs][e], (lane & ~3) + src);
                int   vm = __shfl_sync(FULL, tm[rs][e], (lane & ~3) + src);
                if ((lane & 3) == 0) {
                    if (vs < m4s[3]) {
                        if (vs < m4s[1]) {
                            if (vs < m4s[0]) {
                                m4s[3]=m4s[2]; m4i[3]=m4i[2]; m4s[2]=m4s[1]; m4i[2]=m4i[1];
                                m4s[1]=m4s[0]; m4i[1]=m4i[0]; m4s[0]=vs; m4i[0]=vm;
                            } else {
                                m4s[3]=m4s[2]; m4i[3]=m4i[2]; m4s[2]=m4s[1]; m4i[2]=m4i[1];
                                m4s[1]=vs; m4i[1]=vm;
                            }
                        } else {
                            if (vs < m4s[2]) { m4s[3]=m4s[2]; m4i[3]=m4i[2]; m4s[2]=vs; m4i[2]=vm; }
                            else             { m4s[3]=vs; m4i[3]=vm; }
                        }
                    }
                }
            }
        }
        if ((lane & 3) == 0) {
            int bn = w * 32 + (rs >> 1) * 16 + (lane >> 2) + (rs & 1) * 8;
            size_t base = ((size_t)bn * Cv + c) * 8 + mh * 4;
            #pragma unroll
            for (int t = 0; t < 4; t++) g_cand[base + t] = mh * 2048 + m4i[t];
        }
    }
}

// ---------------------------------------------------------------------------
__global__ void __launch_bounds__(256) rescore_kernel(const float* __restrict__ cb) {
    int wp   = (blockIdx.x * 256 + threadIdx.x) >> 5;
    int lane = threadIdx.x & 31;
    int bn   = wp >> 8;
    int c    = wp & 255;
    float4 x = *(const float4*)(g_xp + ((size_t)c * BNv + bn) * Ev + lane * 4);
    float best = 3.4e38f; int bm = Mv;
    #pragma unroll
    for (int t = 0; t < 8; t++) {
        int m = g_cand[((size_t)bn * Cv + c) * 8 + t];
        float4 cv = *(const float4*)(cb + ((size_t)c * Mv + m) * Ev + lane * 4);
        float d = x.x * cv.x + x.y * cv.y + x.z * cv.z + x.w * cv.w;
        #pragma unroll
        for (int o = 16; o; o >>= 1) d += __shfl_xor_sync(0xffffffffu, d, o);
        float s = g_esq[(size_t)c * Mv + m] - 2.f * d;
        if (s < best || (s == best && m < bm)) { best = s; bm = m; }
    }
    if (lane == 0) g_idx[(size_t)bn * Cv + c] = bm;
}

// ---------------------------------------------------------------------------
__global__ void __launch_bounds__(256) stage3_kernel(const float* __restrict__ vals,
                                                     float* __restrict__ out) {
    __shared__ float sh[256][Vv];
    const int bn = blockIdx.x;
    const int c  = threadIdx.x;
    int m = g_idx[(size_t)bn * Cv + c];
    const float* vp = vals + ((size_t)c * Mv + m) * Vv;
    #pragma unroll
    for (int v = 0; v < Vv; v++) sh[c][v] = vp[v];
    __syncthreads();
    if (c < Vv) {
        float s = 0.f;
        for (int k = 0; k < 256; k++) s += sh[k][c];
        out[(size_t)bn * Vv + c] = s * (1.f / 256.f);
    }
}

// ---------------------------------------------------------------------------
extern "C" void kernel_launch(void* const* d_in, const int* in_sizes, int n_in,
                              void* d_out, int out_size) {
    const float* emb  = (const float*)d_in[0];
    const float* rp   = (const float*)d_in[1];
    const float* cb   = (const float*)d_in[2];
    const float* vals = (const float*)d_in[3];
    float* out = (float*)d_out;

    cudaFuncSetAttribute(mma_kernel, cudaFuncAttributeMaxDynamicSharedMemorySize, SMEM2);
    cudaFuncSetAttribute(stage1_kernel, cudaFuncAttributeMaxDynamicSharedMemorySize, S1_SMEM);

    prep_kernel<<<(Cv * Mv) / 8, 256>>>(cb);
    stage1_kernel<<<Cv * 2, 256, S1_SMEM>>>(emb, rp);
    mma_kernel<<<Cv * 2, 256, SMEM2>>>();
    rescore_kernel<<<(BNv * Cv) / 8, 256>>>(cb);
    stage3_kernel<<<BNv, 256>>>(vals, out);
}

// round 12
// speedup vs baseline: 1.1116x; 1.0247x over previous
#include <cuda_runtime.h>
#include <cuda_bf16.h>
#include <cstdint>

// Problem constants
#define BNv 256
#define Dv  2048
#define Cv  256
#define Ev  128
#define Mv  4096
#define Vv  10

#define KEXT 144
#define ROWB (KEXT * 2)
#define SSTR 304

// Scratch
__device__ float g_xp[(size_t)Cv * BNv * Ev];
__device__ float g_esq[(size_t)Cv * Mv];
__device__ int   g_idx[(size_t)BNv * Cv];
__device__ int   g_cand[(size_t)BNv * Cv * 8];
__device__ __align__(16) unsigned char g_cbb[(size_t)Cv * Mv * ROWB];

// ---------------------------------------------------------------------------
__device__ __forceinline__ uint32_t smem_u32(const void* p) {
    uint32_t a;
    asm("{ .reg .u64 t; cvta.to.shared.u64 t, %1; cvt.u32.u64 %0, t; }" : "=r"(a) : "l"(p));
    return a;
}
__device__ __forceinline__ void cp16(uint32_t dst, const void* src) {
    asm volatile("cp.async.cg.shared.global [%0], [%1], 16;" :: "r"(dst), "l"(src) : "memory");
}
__device__ __forceinline__ void cp_commit() { asm volatile("cp.async.commit_group;" ::: "memory"); }
__device__ __forceinline__ void cp_wait0()  { asm volatile("cp.async.wait_group 0;"  ::: "memory"); }

__device__ __forceinline__ void ldm4(uint32_t& r0, uint32_t& r1, uint32_t& r2, uint32_t& r3, uint32_t a) {
    asm volatile("ldmatrix.sync.aligned.m8n8.x4.shared.b16 {%0,%1,%2,%3}, [%4];"
                 : "=r"(r0), "=r"(r1), "=r"(r2), "=r"(r3) : "r"(a));
}
__device__ __forceinline__ void mma16816(float* c, const uint32_t* a, uint32_t b0, uint32_t b1) {
    asm volatile("mma.sync.aligned.m16n8k16.row.col.f32.bf16.bf16.f32 "
                 "{%0,%1,%2,%3}, {%4,%5,%6,%7}, {%8,%9}, {%0,%1,%2,%3};"
                 : "+f"(c[0]), "+f"(c[1]), "+f"(c[2]), "+f"(c[3])
                 : "r"(a[0]), "r"(a[1]), "r"(a[2]), "r"(a[3]), "r"(b0), "r"(b1));
}
__device__ __forceinline__ uint32_t pack_bf2(float x, float y) {
    return ((uint32_t)__bfloat16_as_ushort(__float2bfloat16(y)) << 16) |
           __bfloat16_as_ushort(__float2bfloat16(x));
}
// packed fp32x2 helpers (Blackwell FFMA2) -- each lane is an exact fp32 RN fma
__device__ __forceinline__ unsigned long long pack_ff(float x, float y) {
    unsigned long long r;
    asm("mov.b64 %0, {%1, %2};" : "=l"(r) : "f"(x), "f"(y));
    return r;
}
__device__ __forceinline__ void unpack_ff(unsigned long long d, float& x, float& y) {
    asm("mov.b64 {%0, %1}, %2;" : "=f"(x), "=f"(y) : "l"(d));
}
__device__ __forceinline__ void ffma2(unsigned long long& d, unsigned long long a, unsigned long long b) {
    asm("fma.rn.f32x2 %0, %1, %2, %0;" : "+l"(d) : "l"(a), "l"(b));
}

// ---------------------------------------------------------------------------
// stage1 + prep, grid-level fused:
//   blocks [0, 512): xp = emb . rp via packed FFMA2 (VERBATIM R9 path --
//     bitwise sequential-k fp32 chain; 1400us-passing version untouched)
//   blocks [512, 4608): codebook -> bf16 ext rows + g_esq (verbatim prep),
//     scheduled into stage1's idle bandwidth (stage1 blocks dispatch first).
// ---------------------------------------------------------------------------
__global__ void __launch_bounds__(256, 2) stage1_kernel(const float* __restrict__ emb,
                                                        const float* __restrict__ rp,
                                                        const float* __restrict__ cb) {
    __shared__ __align__(16) float As[16][130];   // [k][bn]
    __shared__ __align__(16) float Bs[16][132];   // [k][e]

    const int t = threadIdx.x;

    if (blockIdx.x >= 512) {
        // ---------------- prep path (verbatim prep_kernel body) ----------
        const int pb = blockIdx.x - 512;
        int row  = (pb * 256 + t) >> 5;
        int lane = t & 31;
        float4 v = *(const float4*)(cb + (size_t)row * Ev + lane * 4);
        float s = v.x * v.x + v.y * v.y + v.z * v.z + v.w * v.w;
        #pragma unroll
        for (int o = 16; o; o >>= 1) s += __shfl_xor_sync(0xffffffffu, s, o);

        unsigned char* dst = g_cbb + (size_t)row * ROWB;
        uint2 u;
        u.x = pack_bf2(v.x, v.y);
        u.y = pack_bf2(v.z, v.w);
        *(uint2*)(dst + lane * 8) = u;

        if (lane == 0) {
            g_esq[row] = s;
            __nv_bfloat16 hi = __float2bfloat16(s);
            float lo = s - __bfloat162float(hi);
            *(uint32_t*)(dst + 256) =
                ((uint32_t)__bfloat16_as_ushort(__float2bfloat16(lo)) << 16) |
                __bfloat16_as_ushort(hi);
        } else if (lane < 8) {
            *(uint32_t*)(dst + 256 + lane * 4) = 0u;
        }
        return;
    }

    // ---------------- stage1 path (verbatim R9) --------------------------
    const int c = blockIdx.x >> 1;
    const int bn0g = (blockIdx.x & 1) * 128;
    const float* __restrict__ bb = rp + (size_t)c * (Dv * Ev);

    const int wid  = t >> 5, lane = t & 31;
    const int wbn  = wid & 3;          // bn-warp (0..3) * 32
    const int we   = wid >> 2;         // e-warp  (0..1) * 64
    const int g    = lane >> 3;        // bn subgroup *8
    const int el   = lane & 7;         // e lane

    const int arow = t >> 1;           // 0..127
    const int akq  = (t & 1) * 8;      // k offset 0 or 8
    const int bk   = t >> 4;           // 0..15
    const int be   = (t & 15) * 8;     // e offset

    const float* __restrict__ aptr = emb + (size_t)(bn0g + arow) * Dv + akq;
    const float* __restrict__ bptr = bb + (size_t)bk * Ev + be;

    float4 av0 = *(const float4*)(aptr);
    float4 av1 = *(const float4*)(aptr + 4);
    float4 bv0 = *(const float4*)(bptr);
    float4 bv1 = *(const float4*)(bptr + 4);

    unsigned long long acc2[4][8];
    #pragma unroll
    for (int p = 0; p < 4; p++)
        #pragma unroll
        for (int j = 0; j < 8; j++) acc2[p][j] = 0ull;

    const int abase = wbn * 32 + g * 8;
    const int ebase = we * 64 + el;

    for (int k0 = 0; k0 < Dv; k0 += 16) {
        __syncthreads();   // previous tile fully consumed
        As[akq + 0][arow] = av0.x;
        As[akq + 1][arow] = av0.y;
        As[akq + 2][arow] = av0.z;
        As[akq + 3][arow] = av0.w;
        As[akq + 4][arow] = av1.x;
        As[akq + 5][arow] = av1.y;
        As[akq + 6][arow] = av1.z;
        As[akq + 7][arow] = av1.w;
        *(float4*)&Bs[bk][be]     = bv0;
        *(float4*)&Bs[bk][be + 4] = bv1;
        __syncthreads();

        if (k0 + 16 < Dv) {
            av0 = *(const float4*)(aptr + (k0 + 16));
            av1 = *(const float4*)(aptr + (k0 + 16) + 4);
            bv0 = *(const float4*)(bptr + (size_t)(k0 + 16) * Ev);
            bv1 = *(const float4*)(bptr + (size_t)(k0 + 16) * Ev + 4);
        }

        #pragma unroll
        for (int kk = 0; kk < 16; kk++) {
            unsigned long long a2[4], b2[8];
            #pragma unroll
            for (int p = 0; p < 4; p++)
                a2[p] = *(const unsigned long long*)&As[kk][abase + 2 * p];
            #pragma unroll
            for (int j = 0; j < 8; j++) {
                float bf = Bs[kk][ebase + 8 * j];
                b2[j] = pack_ff(bf, bf);
            }
            #pragma unroll
            for (int p = 0; p < 4; p++)
                #pragma unroll
                for (int j = 0; j < 8; j++)
                    ffma2(acc2[p][j], a2[p], b2[j]);
        }
    }

    // store xp: pair (bn, bn+1) same e
    #pragma unroll
    for (int p = 0; p < 4; p++) {
        const int bn = bn0g + abase + 2 * p;
        #pragma unroll
        for (int j = 0; j < 8; j++) {
            float v0, v1;
            unpack_ff(acc2[p][j], v0, v1);
            const size_t base = ((size_t)c * BNv + bn) * Ev + ebase + 8 * j;
            g_xp[base]      = v0;
            g_xp[base + Ev] = v1;
        }
    }
}

// ---------------------------------------------------------------------------
// mma stage (stage2): bf16 candidates, unchanged (passed R3/R9)
// ---------------------------------------------------------------------------
#define XS_BYTES (256 * SSTR)
#define CB_BYTES (64 * SSTR)
#define SMEM2 (XS_BYTES + 2 * CB_BYTES)

__global__ void __launch_bounds__(256, 1) mma_kernel() {
    extern __shared__ __align__(16) unsigned char sm[];
    const uint32_t smb = smem_u32(sm);
    const int tid  = threadIdx.x;
    const int w    = tid >> 5;
    const int lane = tid & 31;
    const int c  = blockIdx.x >> 1;
    const int mh = blockIdx.x & 1;

    {
        const int r = tid;
        const float* xr = g_xp + ((size_t)c * BNv + r) * Ev;
        unsigned char* xd = sm + (size_t)r * SSTR;
        #pragma unroll 8
        for (int q = 0; q < 32; q++) {
            float4 v = *(const float4*)(xr + q * 4);
            uint2 u;
            u.x = pack_bf2(-2.f * v.x, -2.f * v.y);
            u.y = pack_bf2(-2.f * v.z, -2.f * v.w);
            *(uint2*)(xd + q * 8) = u;
        }
        *(uint32_t*)(xd + 256) = 0x3F803F80u;
        #pragma unroll
        for (int t = 0; t < 7; t++) *(uint32_t*)(xd + 260 + t * 4) = 0u;
    }

    const size_t cb_base = (size_t)(c * Mv + mh * 2048) * ROWB;
    const uint32_t cbs = smb + XS_BYTES;
    {
        #pragma unroll
        for (int s = 0; s < 5; s++) {
            int idx = tid + s * 256;
            if (idx < 1152) {
                int row = idx / 18, ch = idx % 18;
                cp16(cbs + row * SSTR + ch * 16, g_cbb + cb_base + (size_t)row * ROWB + ch * 16);
            }
        }
        cp_commit();
    }

    const int grp = lane >> 3;
    const uint32_t a_off = ((grp & 1) * 8 + (lane & 7)) * SSTR + (grp >> 1) * 16;
    const uint32_t b_off = ((grp >> 1) * 8 + (lane & 7)) * SSTR + (grp & 1) * 16;
    const uint32_t xw = smb + (w * 32) * SSTR + a_off;

    float ts[4][3];
    int   tm[4][3];
    #pragma unroll
    for (int r = 0; r < 4; r++)
        #pragma unroll
        for (int e = 0; e < 3; e++) { ts[r][e] = 3.4e38f; tm[r][e] = 0; }

    for (int it = 0; it < 32; it++) {
        const int buf = it & 1;
        cp_wait0();
        __syncthreads();
        if (it < 31) {
            const uint32_t dst = cbs + (buf ^ 1) * CB_BYTES;
            const size_t src = cb_base + (size_t)(it + 1) * 64 * ROWB;
            #pragma unroll
            for (int s = 0; s < 5; s++) {
                int idx = tid + s * 256;
                if (idx < 1152) {
                    int row = idx / 18, ch = idx % 18;
                    cp16(dst + row * SSTR + ch * 16, g_cbb + src + (size_t)row * ROWB + ch * 16);
                }
            }
            cp_commit();
        }

        float acc[2][8][4];
        #pragma unroll
        for (int i = 0; i < 2; i++)
            #pragma unroll
            for (int j = 0; j < 8; j++)
                #pragma unroll
                for (int e = 0; e < 4; e++) acc[i][j][e] = 0.f;

        const uint32_t cw = cbs + buf * CB_BYTES + b_off;

        #pragma unroll
        for (int ks = 0; ks < 9; ks++) {
            uint32_t A[2][4], B[8][2];
            #pragma unroll
            for (int i = 0; i < 2; i++)
                ldm4(A[i][0], A[i][1], A[i][2], A[i][3], xw + i * 16 * SSTR + ks * 32);
            #pragma unroll
            for (int jj = 0; jj < 4; jj++) {
                uint32_t r0, r1, r2, r3;
                ldm4(r0, r1, r2, r3, cw + jj * 16 * SSTR + ks * 32);
                B[2 * jj][0] = r0; B[2 * jj][1] = r1;
                B[2 * jj + 1][0] = r2; B[2 * jj + 1][1] = r3;
            }
            #pragma unroll
            for (int i = 0; i < 2; i++)
                #pragma unroll
                for (int j = 0; j < 8; j++)
                    mma16816(acc[i][j], A[i], B[j][0], B[j][1]);
        }

        const int mb = it * 64 + (lane & 3) * 2;
        #pragma unroll
        for (int i = 0; i < 2; i++)
            #pragma unroll
            for (int j = 0; j < 8; j++) {
                const int m0 = mb + j * 8;
                #pragma unroll
                for (int half = 0; half < 2; half++) {
                    const int rs = i * 2 + half;
                    #pragma unroll
                    for (int e = 0; e < 2; e++) {
                        float v = acc[i][j][half * 2 + e];
                        int   m = m0 + e;
                        if (v < ts[rs][2]) {
                            if (v < ts[rs][1]) {
                                if (v < ts[rs][0]) {
                                    ts[rs][2]=ts[rs][1]; tm[rs][2]=tm[rs][1];
                                    ts[rs][1]=ts[rs][0]; tm[rs][1]=tm[rs][0];
                                    ts[rs][0]=v; tm[rs][0]=m;
                                } else {
                                    ts[rs][2]=ts[rs][1]; tm[rs][2]=tm[rs][1];
                                    ts[rs][1]=v; tm[rs][1]=m;
                                }
                            } else { ts[rs][2]=v; tm[rs][2]=m; }
                        }
                    }
                }
            }
        __syncthreads();
    }

    const uint32_t FULL = 0xffffffffu;
    #pragma unroll
    for (int rs = 0; rs < 4; rs++) {
        float m4s[4] = {3.4e38f, 3.4e38f, 3.4e38f, 3.4e38f};
        int   m4i[4] = {0, 0, 0, 0};
        #pragma unroll
        for (int src = 0; src < 4; src++) {
            #pragma unroll
            for (int e = 0; e < 3; e++) {
                float vs = __shfl_sync(FULL, ts[rs][e], (lane & ~3) + src);
                int   vm = __shfl_sync(FULL, tm[rs][e], (lane & ~3) + src);
                if ((lane & 3) == 0) {
                    if (vs < m4s[3]) {
                        if (vs < m4s[1]) {
                            if (vs < m4s[0]) {
                                m4s[3]=m4s[2]; m4i[3]=m4i[2]; m4s[2]=m4s[1]; m4i[2]=m4i[1];
                                m4s[1]=m4s[0]; m4i[1]=m4i[0]; m4s[0]=vs; m4i[0]=vm;
                            } else {
                                m4s[3]=m4s[2]; m4i[3]=m4i[2]; m4s[2]=m4s[1]; m4i[2]=m4i[1];
                                m4s[1]=vs; m4i[1]=vm;
                            }
                        } else {
                            if (vs < m4s[2]) { m4s[3]=m4s[2]; m4i[3]=m4i[2]; m4s[2]=vs; m4i[2]=vm; }
                            else             { m4s[3]=vs; m4i[3]=vm; }
                        }
                    }
                }
            }
        }
        if ((lane & 3) == 0) {
            int bn = w * 32 + (rs >> 1) * 16 + (lane >> 2) + (rs & 1) * 8;
            size_t base = ((size_t)bn * Cv + c) * 8 + mh * 4;
            #pragma unroll
            for (int t = 0; t < 4; t++) g_cand[base + t] = mh * 2048 + m4i[t];
        }
    }
}

// ---------------------------------------------------------------------------
__global__ void __launch_bounds__(256) rescore_kernel(const float* __restrict__ cb) {
    int wp   = (blockIdx.x * 256 + threadIdx.x) >> 5;
    int lane = threadIdx.x & 31;
    int bn   = wp >> 8;
    int c    = wp & 255;
    float4 x = *(const float4*)(g_xp + ((size_t)c * BNv + bn) * Ev + lane * 4);
    float best = 3.4e38f; int bm = Mv;
    #pragma unroll
    for (int t = 0; t < 8; t++) {
        int m = g_cand[((size_t)bn * Cv + c) * 8 + t];
        float4 cv = *(const float4*)(cb + ((size_t)c * Mv + m) * Ev + lane * 4);
        float d = x.x * cv.x + x.y * cv.y + x.z * cv.z + x.w * cv.w;
        #pragma unroll
        for (int o = 16; o; o >>= 1) d += __shfl_xor_sync(0xffffffffu, d, o);
        float s = g_esq[(size_t)c * Mv + m] - 2.f * d;
        if (s < best || (s == best && m < bm)) { best = s; bm = m; }
    }
    if (lane == 0) g_idx[(size_t)bn * Cv + c] = bm;
}

// ---------------------------------------------------------------------------
__global__ void __launch_bounds__(256) stage3_kernel(const float* __restrict__ vals,
                                                     float* __restrict__ out) {
    __shared__ float sh[256][Vv];
    const int bn = blockIdx.x;
    const int c  = threadIdx.x;
    int m = g_idx[(size_t)bn * Cv + c];
    const float* vp = vals + ((size_t)c * Mv + m) * Vv;
    #pragma unroll
    for (int v = 0; v < Vv; v++) sh[c][v] = vp[v];
    __syncthreads();
    if (c < Vv) {
        float s = 0.f;
        for (int k = 0; k < 256; k++) s += sh[k][c];
        out[(size_t)bn * Vv + c] = s * (1.f / 256.f);
    }
}

// ---------------------------------------------------------------------------
extern "C" void kernel_launch(void* const* d_in, const int* in_sizes, int n_in,
                              void* d_out, int out_size) {
    const float* emb  = (const float*)d_in[0];
    const float* rp   = (const float*)d_in[1];
    const float* cb   = (const float*)d_in[2];
    const float* vals = (const float*)d_in[3];
    float* out = (float*)d_out;

    cudaFuncSetAttribute(mma_kernel, cudaFuncAttributeMaxDynamicSharedMemorySize, SMEM2);

    stage1_kernel<<<512 + (Cv * Mv) / 8, 256>>>(emb, rp, cb);
    mma_kernel<<<Cv * 2, 256, SMEM2>>>();
    rescore_kernel<<<(BNv * Cv) / 8, 256>>>(cb);
    stage3_kernel<<<BNv, 256>>>(vals, out);
}

// round 13
// speedup vs baseline: 1.1521x; 1.0364x over previous
#include <cuda_runtime.h>
#include <cuda_bf16.h>
#include <cstdint>

// Problem constants
#define BNv 256
#define Dv  2048
#define Cv  256
#define Ev  128
#define Mv  4096
#define Vv  10

#define KEXT 144
#define ROWB (KEXT * 2)
#define SSTR 304

// Scratch
__device__ float g_xp[(size_t)Cv * BNv * Ev];
__device__ float g_esq[(size_t)Cv * Mv];
__device__ int   g_idx[(size_t)BNv * Cv];
__device__ int   g_cand[(size_t)BNv * Cv * 8];
__device__ __align__(16) unsigned char g_cbb[(size_t)Cv * Mv * ROWB];

// ---------------------------------------------------------------------------
__device__ __forceinline__ uint32_t smem_u32(const void* p) {
    uint32_t a;
    asm("{ .reg .u64 t; cvta.to.shared.u64 t, %1; cvt.u32.u64 %0, t; }" : "=r"(a) : "l"(p));
    return a;
}
__device__ __forceinline__ void cp16(uint32_t dst, const void* src) {
    asm volatile("cp.async.cg.shared.global [%0], [%1], 16;" :: "r"(dst), "l"(src) : "memory");
}
__device__ __forceinline__ void cp_commit() { asm volatile("cp.async.commit_group;" ::: "memory"); }
__device__ __forceinline__ void cp_wait0()  { asm volatile("cp.async.wait_group 0;"  ::: "memory"); }

__device__ __forceinline__ void ldm4(uint32_t& r0, uint32_t& r1, uint32_t& r2, uint32_t& r3, uint32_t a) {
    asm volatile("ldmatrix.sync.aligned.m8n8.x4.shared.b16 {%0,%1,%2,%3}, [%4];"
                 : "=r"(r0), "=r"(r1), "=r"(r2), "=r"(r3) : "r"(a));
}
__device__ __forceinline__ void mma16816(float* c, const uint32_t* a, uint32_t b0, uint32_t b1) {
    asm volatile("mma.sync.aligned.m16n8k16.row.col.f32.bf16.bf16.f32 "
                 "{%0,%1,%2,%3}, {%4,%5,%6,%7}, {%8,%9}, {%0,%1,%2,%3};"
                 : "+f"(c[0]), "+f"(c[1]), "+f"(c[2]), "+f"(c[3])
                 : "r"(a[0]), "r"(a[1]), "r"(a[2]), "r"(a[3]), "r"(b0), "r"(b1));
}
__device__ __forceinline__ uint32_t pack_bf2(float x, float y) {
    return ((uint32_t)__bfloat16_as_ushort(__float2bfloat16(y)) << 16) |
           __bfloat16_as_ushort(__float2bfloat16(x));
}
// packed fp32x2 helpers (Blackwell FFMA2) -- each lane is an exact fp32 RN fma
__device__ __forceinline__ unsigned long long pack_ff(float x, float y) {
    unsigned long long r;
    asm("mov.b64 %0, {%1, %2};" : "=l"(r) : "f"(x), "f"(y));
    return r;
}
__device__ __forceinline__ void unpack_ff(unsigned long long d, float& x, float& y) {
    asm("mov.b64 {%0, %1}, %2;" : "=f"(x), "=f"(y) : "l"(d));
}
__device__ __forceinline__ void ffma2(unsigned long long& d, unsigned long long a, unsigned long long b) {
    asm("fma.rn.f32x2 %0, %1, %2, %0;" : "+l"(d) : "l"(a), "l"(b));
}

// ---------------------------------------------------------------------------
// prep: codebook -> bf16 ext rows [cb | esq_hi | esq_lo | zeros], + g_esq
// (separate kernel; fusing into stage1 regressed twice -- R10/R12)
// ---------------------------------------------------------------------------
__global__ void __launch_bounds__(256) prep_kernel(const float* __restrict__ cb) {
    int row  = (blockIdx.x * 256 + threadIdx.x) >> 5;
    int lane = threadIdx.x & 31;
    float4 v = *(const float4*)(cb + (size_t)row * Ev + lane * 4);
    float s = v.x * v.x + v.y * v.y + v.z * v.z + v.w * v.w;
    #pragma unroll
    for (int o = 16; o; o >>= 1) s += __shfl_xor_sync(0xffffffffu, s, o);

    unsigned char* dst = g_cbb + (size_t)row * ROWB;
    uint2 u;
    u.x = pack_bf2(v.x, v.y);
    u.y = pack_bf2(v.z, v.w);
    *(uint2*)(dst + lane * 8) = u;

    if (lane == 0) {
        g_esq[row] = s;
        __nv_bfloat16 hi = __float2bfloat16(s);
        float lo = s - __bfloat162float(hi);
        *(uint32_t*)(dst + 256) =
            ((uint32_t)__bfloat16_as_ushort(__float2bfloat16(lo)) << 16) |
            __bfloat16_as_ushort(hi);
    } else if (lane < 8) {
        *(uint32_t*)(dst + 256 + lane * 4) = 0u;
    }
}

// ---------------------------------------------------------------------------
// stage1: xp = emb . rp via packed FFMA2 (VERBATIM R9 -- 1400us passing).
// ---------------------------------------------------------------------------
__global__ void __launch_bounds__(256, 2) stage1_kernel(const float* __restrict__ emb,
                                                        const float* __restrict__ rp) {
    __shared__ __align__(16) float As[16][130];   // [k][bn]
    __shared__ __align__(16) float Bs[16][132];   // [k][e]

    const int t = threadIdx.x;
    const int c = blockIdx.x >> 1;
    const int bn0g = (blockIdx.x & 1) * 128;
    const float* __restrict__ bb = rp + (size_t)c * (Dv * Ev);

    const int wid  = t >> 5, lane = t & 31;
    const int wbn  = wid & 3;
    const int we   = wid >> 2;
    const int g    = lane >> 3;
    const int el   = lane & 7;

    const int arow = t >> 1;
    const int akq  = (t & 1) * 8;
    const int bk   = t >> 4;
    const int be   = (t & 15) * 8;

    const float* __restrict__ aptr = emb + (size_t)(bn0g + arow) * Dv + akq;
    const float* __restrict__ bptr = bb + (size_t)bk * Ev + be;

    float4 av0 = *(const float4*)(aptr);
    float4 av1 = *(const float4*)(aptr + 4);
    float4 bv0 = *(const float4*)(bptr);
    float4 bv1 = *(const float4*)(bptr + 4);

    unsigned long long acc2[4][8];
    #pragma unroll
    for (int p = 0; p < 4; p++)
        #pragma unroll
        for (int j = 0; j < 8; j++) acc2[p][j] = 0ull;

    const int abase = wbn * 32 + g * 8;
    const int ebase = we * 64 + el;

    for (int k0 = 0; k0 < Dv; k0 += 16) {
        __syncthreads();
        As[akq + 0][arow] = av0.x;
        As[akq + 1][arow] = av0.y;
        As[akq + 2][arow] = av0.z;
        As[akq + 3][arow] = av0.w;
        As[akq + 4][arow] = av1.x;
        As[akq + 5][arow] = av1.y;
        As[akq + 6][arow] = av1.z;
        As[akq + 7][arow] = av1.w;
        *(float4*)&Bs[bk][be]     = bv0;
        *(float4*)&Bs[bk][be + 4] = bv1;
        __syncthreads();

        if (k0 + 16 < Dv) {
            av0 = *(const float4*)(aptr + (k0 + 16));
            av1 = *(const float4*)(aptr + (k0 + 16) + 4);
            bv0 = *(const float4*)(bptr + (size_t)(k0 + 16) * Ev);
            bv1 = *(const float4*)(bptr + (size_t)(k0 + 16) * Ev + 4);
        }

        #pragma unroll
        for (int kk = 0; kk < 16; kk++) {
            unsigned long long a2[4], b2[8];
            #pragma unroll
            for (int p = 0; p < 4; p++)
                a2[p] = *(const unsigned long long*)&As[kk][abase + 2 * p];
            #pragma unroll
            for (int j = 0; j < 8; j++) {
                float bf = Bs[kk][ebase + 8 * j];
                b2[j] = pack_ff(bf, bf);
            }
            #pragma unroll
            for (int p = 0; p < 4; p++)
                #pragma unroll
                for (int j = 0; j < 8; j++)
                    ffma2(acc2[p][j], a2[p], b2[j]);
        }
    }

    #pragma unroll
    for (int p = 0; p < 4; p++) {
        const int bn = bn0g + abase + 2 * p;
        #pragma unroll
        for (int j = 0; j < 8; j++) {
            float v0, v1;
            unpack_ff(acc2[p][j], v0, v1);
            const size_t base = ((size_t)c * BNv + bn) * Ev + ebase + 8 * j;
            g_xp[base]      = v0;
            g_xp[base + Ev] = v1;
        }
    }
}

// ---------------------------------------------------------------------------
// mma stage (stage2): bf16 candidates. ONLY change vs R9: epilogue uses an
// FMNMX min-tree early-out before the exact top-3 insertion (identical
// candidate semantics: any insert requires v < ts[2] => min16 < ts[2]).
// ---------------------------------------------------------------------------
#define XS_BYTES (256 * SSTR)
#define CB_BYTES (64 * SSTR)
#define SMEM2 (XS_BYTES + 2 * CB_BYTES)

__global__ void __launch_bounds__(256, 1) mma_kernel() {
    extern __shared__ __align__(16) unsigned char sm[];
    const uint32_t smb = smem_u32(sm);
    const int tid  = threadIdx.x;
    const int w    = tid >> 5;
    const int lane = tid & 31;
    const int c  = blockIdx.x >> 1;
    const int mh = blockIdx.x & 1;

    {
        const int r = tid;
        const float* xr = g_xp + ((size_t)c * BNv + r) * Ev;
        unsigned char* xd = sm + (size_t)r * SSTR;
        #pragma unroll 8
        for (int q = 0; q < 32; q++) {
            float4 v = *(const float4*)(xr + q * 4);
            uint2 u;
            u.x = pack_bf2(-2.f * v.x, -2.f * v.y);
            u.y = pack_bf2(-2.f * v.z, -2.f * v.w);
            *(uint2*)(xd + q * 8) = u;
        }
        *(uint32_t*)(xd + 256) = 0x3F803F80u;
        #pragma unroll
        for (int t = 0; t < 7; t++) *(uint32_t*)(xd + 260 + t * 4) = 0u;
    }

    const size_t cb_base = (size_t)(c * Mv + mh * 2048) * ROWB;
    const uint32_t cbs = smb + XS_BYTES;
    {
        #pragma unroll
        for (int s = 0; s < 5; s++) {
            int idx = tid + s * 256;
            if (idx < 1152) {
                int row = idx / 18, ch = idx % 18;
                cp16(cbs + row * SSTR + ch * 16, g_cbb + cb_base + (size_t)row * ROWB + ch * 16);
            }
        }
        cp_commit();
    }

    const int grp = lane >> 3;
    const uint32_t a_off = ((grp & 1) * 8 + (lane & 7)) * SSTR + (grp >> 1) * 16;
    const uint32_t b_off = ((grp >> 1) * 8 + (lane & 7)) * SSTR + (grp & 1) * 16;
    const uint32_t xw = smb + (w * 32) * SSTR + a_off;

    float ts[4][3];
    int   tm[4][3];
    #pragma unroll
    for (int r = 0; r < 4; r++)
        #pragma unroll
        for (int e = 0; e < 3; e++) { ts[r][e] = 3.4e38f; tm[r][e] = 0; }

    for (int it = 0; it < 32; it++) {
        const int buf = it & 1;
        cp_wait0();
        __syncthreads();
        if (it < 31) {
            const uint32_t dst = cbs + (buf ^ 1) * CB_BYTES;
            const size_t src = cb_base + (size_t)(it + 1) * 64 * ROWB;
            #pragma unroll
            for (int s = 0; s < 5; s++) {
                int idx = tid + s * 256;
                if (idx < 1152) {
                    int row = idx / 18, ch = idx % 18;
                    cp16(dst + row * SSTR + ch * 16, g_cbb + src + (size_t)row * ROWB + ch * 16);
                }
            }
            cp_commit();
        }

        float acc[2][8][4];
        #pragma unroll
        for (int i = 0; i < 2; i++)
            #pragma unroll
            for (int j = 0; j < 8; j++)
                #pragma unroll
                for (int e = 0; e < 4; e++) acc[i][j][e] = 0.f;

        const uint32_t cw = cbs + buf * CB_BYTES + b_off;

        #pragma unroll
        for (int ks = 0; ks < 9; ks++) {
            uint32_t A[2][4], B[8][2];
            #pragma unroll
            for (int i = 0; i < 2; i++)
                ldm4(A[i][0], A[i][1], A[i][2], A[i][3], xw + i * 16 * SSTR + ks * 32);
            #pragma unroll
            for (int jj = 0; jj < 4; jj++) {
                uint32_t r0, r1, r2, r3;
                ldm4(r0, r1, r2, r3, cw + jj * 16 * SSTR + ks * 32);
                B[2 * jj][0] = r0; B[2 * jj][1] = r1;
                B[2 * jj + 1][0] = r2; B[2 * jj + 1][1] = r3;
            }
            #pragma unroll
            for (int i = 0; i < 2; i++)
                #pragma unroll
                for (int j = 0; j < 8; j++)
                    mma16816(acc[i][j], A[i], B[j][0], B[j][1]);
        }

        // epilogue: min-tree early-out, then exact insert (rare path)
        const int mb = it * 64 + (lane & 3) * 2;
        #pragma unroll
        for (int rs = 0; rs < 4; rs++) {
            const int i = rs >> 1, half = rs & 1;
            float mn = acc[i][0][half * 2];
            #pragma unroll
            for (int j = 0; j < 8; j++) {
                mn = fminf(mn, acc[i][j][half * 2]);
                mn = fminf(mn, acc[i][j][half * 2 + 1]);
            }
            if (mn < ts[rs][2]) {
                #pragma unroll
                for (int j = 0; j < 8; j++) {
                    const int m0 = mb + j * 8;
                    #pragma unroll
                    for (int e = 0; e < 2; e++) {
                        float v = acc[i][j][half * 2 + e];
                        int   m = m0 + e;
                        if (v < ts[rs][2]) {
                            if (v < ts[rs][1]) {
                                if (v < ts[rs][0]) {
                                    ts[rs][2]=ts[rs][1]; tm[rs][2]=tm[rs][1];
                                    ts[rs][1]=ts[rs][0]; tm[rs][1]=tm[rs][0];
                                    ts[rs][0]=v; tm[rs][0]=m;
                                } else {
                                    ts[rs][2]=ts[rs][1]; tm[rs][2]=tm[rs][1];
                                    ts[rs][1]=v; tm[rs][1]=m;
                                }
                            } else { ts[rs][2]=v; tm[rs][2]=m; }
                        }
                    }
                }
            }
        }
        __syncthreads();
    }

    const uint32_t FULL = 0xffffffffu;
    #pragma unroll
    for (int rs = 0; rs < 4; rs++) {
        float m4s[4] = {3.4e38f, 3.4e38f, 3.4e38f, 3.4e38f};
        int   m4i[4] = {0, 0, 0, 0};
        #pragma unroll
        for (int src = 0; src < 4; src++) {
            #pragma unroll
            for (int e = 0; e < 3; e++) {
                float vs = __shfl_sync(FULL, ts[rs][e], (lane & ~3) + src);
                int   vm = __shfl_sync(FULL, tm[rs][e], (lane & ~3) + src);
                if ((lane & 3) == 0) {
                    if (vs < m4s[3]) {
                        if (vs < m4s[1]) {
                            if (vs < m4s[0]) {
                                m4s[3]=m4s[2]; m4i[3]=m4i[2]; m4s[2]=m4s[1]; m4i[2]=m4i[1];
                                m4s[1]=m4s[0]; m4i[1]=m4i[0]; m4s[0]=vs; m4i[0]=vm;
                            } else {
                                m4s[3]=m4s[2]; m4i[3]=m4i[2]; m4s[2]=m4s[1]; m4i[2]=m4i[1];
                                m4s[1]=vs; m4i[1]=vm;
                            }
                        } else {
                            if (vs < m4s[2]) { m4s[3]=m4s[2]; m4i[3]=m4i[2]; m4s[2]=vs; m4i[2]=vm; }
                            else             { m4s[3]=vs; m4i[3]=vm; }
                        }
                    }
                }
            }
        }
        if ((lane & 3) == 0) {
            int bn = w * 32 + (rs >> 1) * 16 + (lane >> 2) + (rs & 1) * 8;
            size_t base = ((size_t)bn * Cv + c) * 8 + mh * 4;
            #pragma unroll
            for (int t = 0; t < 4; t++) g_cand[base + t] = mh * 2048 + m4i[t];
        }
    }
}

// ---------------------------------------------------------------------------
__global__ void __launch_bounds__(256) rescore_kernel(const float* __restrict__ cb) {
    int wp   = (blockIdx.x * 256 + threadIdx.x) >> 5;
    int lane = threadIdx.x & 31;
    int bn   = wp >> 8;
    int c    = wp & 255;
    float4 x = *(const float4*)(g_xp + ((size_t)c * BNv + bn) * Ev + lane * 4);
    float best = 3.4e38f; int bm = Mv;
    #pragma unroll
    for (int t = 0; t < 8; t++) {
        int m = g_cand[((size_t)bn * Cv + c) * 8 + t];
        float4 cv = *(const float4*)(cb + ((size_t)c * Mv + m) * Ev + lane * 4);
        float d = x.x * cv.x + x.y * cv.y + x.z * cv.z + x.w * cv.w;
        #pragma unroll
        for (int o = 16; o; o >>= 1) d += __shfl_xor_sync(0xffffffffu, d, o);
        float s = g_esq[(size_t)c * Mv + m] - 2.f * d;
        if (s < best || (s == best && m < bm)) { best = s; bm = m; }
    }
    if (lane == 0) g_idx[(size_t)bn * Cv + c] = bm;
}

// ---------------------------------------------------------------------------
__global__ void __launch_bounds__(256) stage3_kernel(const float* __restrict__ vals,
                                                     float* __restrict__ out) {
    __shared__ float sh[256][Vv];
    const int bn = blockIdx.x;
    const int c  = threadIdx.x;
    int m = g_idx[(size_t)bn * Cv + c];
    const float* vp = vals + ((size_t)c * Mv + m) * Vv;
    #pragma unroll
    for (int v = 0; v < Vv; v++) sh[c][v] = vp[v];
    __syncthreads();
    if (c < Vv) {
        float s = 0.f;
        for (int k = 0; k < 256; k++) s += sh[k][c];
        out[(size_t)bn * Vv + c] = s * (1.f / 256.f);
    }
}

// ---------------------------------------------------------------------------
extern "C" void kernel_launch(void* const* d_in, const int* in_sizes, int n_in,
                              void* d_out, int out_size) {
    const float* emb  = (const float*)d_in[0];
    const float* rp   = (const float*)d_in[1];
    const float* cb   = (const float*)d_in[2];
    const float* vals = (const float*)d_in[3];
    float* out = (float*)d_out;

    cudaFuncSetAttribute(mma_kernel, cudaFuncAttributeMaxDynamicSharedMemorySize, SMEM2);

    prep_kernel<<<(Cv * Mv) / 8, 256>>>(cb);
    stage1_kernel<<<Cv * 2, 256>>>(emb, rp);
    mma_kernel<<<Cv * 2, 256, SMEM2>>>();
    rescore_kernel<<<(BNv * Cv) / 8, 256>>>(cb);
    stage3_kernel<<<BNv, 256>>>(vals, out);
}

// round 14
// speedup vs baseline: 1.3818x; 1.1994x over previous
#include <cuda_runtime.h>
#include <cuda_bf16.h>
#include <cstdint>

// Problem constants
#define BNv 256
#define Dv  2048
#define Cv  256
#define Ev  128
#define Mv  4096
#define Vv  10

#define KEXT 144
#define ROWB (KEXT * 2)
#define SSTR 304

// Scratch
__device__ float g_xp[(size_t)Cv * BNv * Ev];
__device__ float g_esq[(size_t)Cv * Mv];
__device__ int   g_idx[(size_t)BNv * Cv];
__device__ int   g_cand[(size_t)BNv * Cv * 8];
__device__ __align__(16) unsigned char g_cbb[(size_t)Cv * Mv * ROWB];

// ---------------------------------------------------------------------------
__device__ __forceinline__ uint32_t smem_u32(const void* p) {
    uint32_t a;
    asm("{ .reg .u64 t; cvta.to.shared.u64 t, %1; cvt.u32.u64 %0, t; }" : "=r"(a) : "l"(p));
    return a;
}
__device__ __forceinline__ void cp16(uint32_t dst, const void* src) {
    asm volatile("cp.async.cg.shared.global [%0], [%1], 16;" :: "r"(dst), "l"(src) : "memory");
}
__device__ __forceinline__ void cp_commit() { asm volatile("cp.async.commit_group;" ::: "memory"); }
__device__ __forceinline__ void cp_wait0()  { asm volatile("cp.async.wait_group 0;"  ::: "memory"); }

__device__ __forceinline__ void ldm4(uint32_t& r0, uint32_t& r1, uint32_t& r2, uint32_t& r3, uint32_t a) {
    asm volatile("ldmatrix.sync.aligned.m8n8.x4.shared.b16 {%0,%1,%2,%3}, [%4];"
                 : "=r"(r0), "=r"(r1), "=r"(r2), "=r"(r3) : "r"(a));
}
__device__ __forceinline__ void mma16816(float* c, const uint32_t* a, uint32_t b0, uint32_t b1) {
    asm volatile("mma.sync.aligned.m16n8k16.row.col.f32.bf16.bf16.f32 "
                 "{%0,%1,%2,%3}, {%4,%5,%6,%7}, {%8,%9}, {%0,%1,%2,%3};"
                 : "+f"(c[0]), "+f"(c[1]), "+f"(c[2]), "+f"(c[3])
                 : "r"(a[0]), "r"(a[1]), "r"(a[2]), "r"(a[3]), "r"(b0), "r"(b1));
}
__device__ __forceinline__ uint32_t pack_bf2(float x, float y) {
    return ((uint32_t)__bfloat16_as_ushort(__float2bfloat16(y)) << 16) |
           __bfloat16_as_ushort(__float2bfloat16(x));
}
// packed fp32x2 helpers (Blackwell FFMA2) -- each lane is an exact fp32 RN fma
__device__ __forceinline__ unsigned long long pack_ff(float x, float y) {
    unsigned long long r;
    asm("mov.b64 %0, {%1, %2};" : "=l"(r) : "f"(x), "f"(y));
    return r;
}
__device__ __forceinline__ void unpack_ff(unsigned long long d, float& x, float& y) {
    asm("mov.b64 {%0, %1}, %2;" : "=f"(x), "=f"(y) : "l"(d));
}
__device__ __forceinline__ void ffma2(unsigned long long& d, unsigned long long a, unsigned long long b) {
    asm("fma.rn.f32x2 %0, %1, %2, %0;" : "+l"(d) : "l"(a), "l"(b));
}

// ---------------------------------------------------------------------------
// prep: codebook -> bf16 ext rows [cb | esq_hi | esq_lo | zeros], + g_esq
// (VERBATIM R9)
// ---------------------------------------------------------------------------
__global__ void __launch_bounds__(256) prep_kernel(const float* __restrict__ cb) {
    int row  = (blockIdx.x * 256 + threadIdx.x) >> 5;
    int lane = threadIdx.x & 31;
    float4 v = *(const float4*)(cb + (size_t)row * Ev + lane * 4);
    float s = v.x * v.x + v.y * v.y + v.z * v.z + v.w * v.w;
    #pragma unroll
    for (int o = 16; o; o >>= 1) s += __shfl_xor_sync(0xffffffffu, s, o);

    unsigned char* dst = g_cbb + (size_t)row * ROWB;
    uint2 u;
    u.x = pack_bf2(v.x, v.y);
    u.y = pack_bf2(v.z, v.w);
    *(uint2*)(dst + lane * 8) = u;

    if (lane == 0) {
        g_esq[row] = s;
        __nv_bfloat16 hi = __float2bfloat16(s);
        float lo = s - __bfloat162float(hi);
        *(uint32_t*)(dst + 256) =
            ((uint32_t)__bfloat16_as_ushort(__float2bfloat16(lo)) << 16) |
            __bfloat16_as_ushort(hi);
    } else if (lane < 8) {
        *(uint32_t*)(dst + 256 + lane * 4) = 0u;
    }
}

// ---------------------------------------------------------------------------
// stage1: xp = emb . rp via packed FFMA2 (VERBATIM R9 -- frozen).
// ---------------------------------------------------------------------------
__global__ void __launch_bounds__(256, 2) stage1_kernel(const float* __restrict__ emb,
                                                        const float* __restrict__ rp) {
    __shared__ __align__(16) float As[16][130];   // [k][bn]
    __shared__ __align__(16) float Bs[16][132];   // [k][e]

    const int t = threadIdx.x;
    const int c = blockIdx.x >> 1;
    const int bn0g = (blockIdx.x & 1) * 128;
    const float* __restrict__ bb = rp + (size_t)c * (Dv * Ev);

    const int wid  = t >> 5, lane = t & 31;
    const int wbn  = wid & 3;
    const int we   = wid >> 2;
    const int g    = lane >> 3;
    const int el   = lane & 7;

    const int arow = t >> 1;
    const int akq  = (t & 1) * 8;
    const int bk   = t >> 4;
    const int be   = (t & 15) * 8;

    const float* __restrict__ aptr = emb + (size_t)(bn0g + arow) * Dv + akq;
    const float* __restrict__ bptr = bb + (size_t)bk * Ev + be;

    float4 av0 = *(const float4*)(aptr);
    float4 av1 = *(const float4*)(aptr + 4);
    float4 bv0 = *(const float4*)(bptr);
    float4 bv1 = *(const float4*)(bptr + 4);

    unsigned long long acc2[4][8];
    #pragma unroll
    for (int p = 0; p < 4; p++)
        #pragma unroll
        for (int j = 0; j < 8; j++) acc2[p][j] = 0ull;

    const int abase = wbn * 32 + g * 8;
    const int ebase = we * 64 + el;

    for (int k0 = 0; k0 < Dv; k0 += 16) {
        __syncthreads();
        As[akq + 0][arow] = av0.x;
        As[akq + 1][arow] = av0.y;
        As[akq + 2][arow] = av0.z;
        As[akq + 3][arow] = av0.w;
        As[akq + 4][arow] = av1.x;
        As[akq + 5][arow] = av1.y;
        As[akq + 6][arow] = av1.z;
        As[akq + 7][arow] = av1.w;
        *(float4*)&Bs[bk][be]     = bv0;
        *(float4*)&Bs[bk][be + 4] = bv1;
        __syncthreads();

        if (k0 + 16 < Dv) {
            av0 = *(const float4*)(aptr + (k0 + 16));
            av1 = *(const float4*)(aptr + (k0 + 16) + 4);
            bv0 = *(const float4*)(bptr + (size_t)(k0 + 16) * Ev);
            bv1 = *(const float4*)(bptr + (size_t)(k0 + 16) * Ev + 4);
        }

        #pragma unroll
        for (int kk = 0; kk < 16; kk++) {
            unsigned long long a2[4], b2[8];
            #pragma unroll
            for (int p = 0; p < 4; p++)
                a2[p] = *(const unsigned long long*)&As[kk][abase + 2 * p];
            #pragma unroll
            for (int j = 0; j < 8; j++) {
                float bf = Bs[kk][ebase + 8 * j];
                b2[j] = pack_ff(bf, bf);
            }
            #pragma unroll
            for (int p = 0; p < 4; p++)
                #pragma unroll
                for (int j = 0; j < 8; j++)
                    ffma2(acc2[p][j], a2[p], b2[j]);
        }
    }

    #pragma unroll
    for (int p = 0; p < 4; p++) {
        const int bn = bn0g + abase + 2 * p;
        #pragma unroll
        for (int j = 0; j < 8; j++) {
            float v0, v1;
            unpack_ff(acc2[p][j], v0, v1);
            const size_t base = ((size_t)c * BNv + bn) * Ev + ebase + 8 * j;
            g_xp[base]      = v0;
            g_xp[base + Ev] = v1;
        }
    }
}

// ---------------------------------------------------------------------------
// mma stage (stage2): bf16 candidates. vs R9: X tile split in half
// (128 bn rows per block, grid 1024) so smem = 77.8KB -> occupancy 2.
// Per (bn-row, lane-quad) the (m, score) stream is identical to R9 ->
// identical candidates. Epilogue = R9 exact insertion (no early-out).
// blockIdx = c*4 + mh*2 + bnh (bnh innermost -> CB L2 reuse).
// ---------------------------------------------------------------------------
#define XS_BYTES (128 * SSTR)            // 38912
#define CB_BYTES (64 * SSTR)             // 19456
#define SMEM2 (XS_BYTES + 2 * CB_BYTES)  // 77824

__global__ void __launch_bounds__(256, 2) mma_kernel() {
    extern __shared__ __align__(16) unsigned char sm[];
    const uint32_t smb = smem_u32(sm);
    const int tid  = threadIdx.x;
    const int w    = tid >> 5;
    const int lane = tid & 31;
    const int c   = blockIdx.x >> 2;
    const int mh  = (blockIdx.x >> 1) & 1;
    const int bnh = blockIdx.x & 1;

    // X convert: 128 rows, each thread does half a row (16 quads)
    {
        const int r  = tid >> 1;
        const int q0 = (tid & 1) * 16;
        const float* xr = g_xp + ((size_t)(c * BNv + bnh * 128 + r)) * Ev;
        unsigned char* xd = sm + (size_t)r * SSTR;
        #pragma unroll 8
        for (int q = q0; q < q0 + 16; q++) {
            float4 v = *(const float4*)(xr + q * 4);
            uint2 u;
            u.x = pack_bf2(-2.f * v.x, -2.f * v.y);
            u.y = pack_bf2(-2.f * v.z, -2.f * v.w);
            *(uint2*)(xd + q * 8) = u;
        }
        if ((tid & 1) == 0) {
            *(uint32_t*)(xd + 256) = 0x3F803F80u;
            #pragma unroll
            for (int z = 0; z < 7; z++) *(uint32_t*)(xd + 260 + z * 4) = 0u;
        }
    }

    const size_t cb_base = (size_t)(c * Mv + mh * 2048) * ROWB;
    const uint32_t cbs = smb + XS_BYTES;
    {
        #pragma unroll
        for (int s = 0; s < 5; s++) {
            int idx = tid + s * 256;
            if (idx < 1152) {
                int row = idx / 18, ch = idx % 18;
                cp16(cbs + row * SSTR + ch * 16, g_cbb + cb_base + (size_t)row * ROWB + ch * 16);
            }
        }
        cp_commit();
    }

    const int grp = lane >> 3;
    const uint32_t a_off = ((grp & 1) * 8 + (lane & 7)) * SSTR + (grp >> 1) * 16;
    const uint32_t b_off = ((grp >> 1) * 8 + (lane & 7)) * SSTR + (grp & 1) * 16;
    const uint32_t xw = smb + (w * 16) * SSTR + a_off;

    float ts[2][3];
    int   tm[2][3];
    #pragma unroll
    for (int r = 0; r < 2; r++)
        #pragma unroll
        for (int e = 0; e < 3; e++) { ts[r][e] = 3.4e38f; tm[r][e] = 0; }

    for (int it = 0; it < 32; it++) {
        const int buf = it & 1;
        cp_wait0();
        __syncthreads();
        if (it < 31) {
            const uint32_t dst = cbs + (buf ^ 1) * CB_BYTES;
            const size_t src = cb_base + (size_t)(it + 1) * 64 * ROWB;
            #pragma unroll
            for (int s = 0; s < 5; s++) {
                int idx = tid + s * 256;
                if (idx < 1152) {
                    int row = idx / 18, ch = idx % 18;
                    cp16(dst + row * SSTR + ch * 16, g_cbb + src + (size_t)row * ROWB + ch * 16);
                }
            }
            cp_commit();
        }

        float acc[8][4];
        #pragma unroll
        for (int j = 0; j < 8; j++)
            #pragma unroll
            for (int e = 0; e < 4; e++) acc[j][e] = 0.f;

        const uint32_t cw = cbs + buf * CB_BYTES + b_off;

        #pragma unroll
        for (int ks = 0; ks < 9; ks++) {
            uint32_t A[4], B[8][2];
            ldm4(A[0], A[1], A[2], A[3], xw + ks * 32);
            #pragma unroll
            for (int jj = 0; jj < 4; jj++) {
                uint32_t r0, r1, r2, r3;
                ldm4(r0, r1, r2, r3, cw + jj * 16 * SSTR + ks * 32);
                B[2 * jj][0] = r0; B[2 * jj][1] = r1;
                B[2 * jj + 1][0] = r2; B[2 * jj + 1][1] = r3;
            }
            #pragma unroll
            for (int j = 0; j < 8; j++)
                mma16816(acc[j], A, B[j][0], B[j][1]);
        }

        // epilogue: exact top-3 insertion (R9 semantics)
        const int mb = it * 64 + (lane & 3) * 2;
        #pragma unroll
        for (int j = 0; j < 8; j++) {
            const int m0 = mb + j * 8;
            #pragma unroll
            for (int half = 0; half < 2; half++) {
                const int rs = half;
                #pragma unroll
                for (int e = 0; e < 2; e++) {
                    float v = acc[j][half * 2 + e];
                    int   m = m0 + e;
                    if (v < ts[rs][2]) {
                        if (v < ts[rs][1]) {
                            if (v < ts[rs][0]) {
                                ts[rs][2]=ts[rs][1]; tm[rs][2]=tm[rs][1];
                                ts[rs][1]=ts[rs][0]; tm[rs][1]=tm[rs][0];
                                ts[rs][0]=v; tm[rs][0]=m;
                            } else {
                                ts[rs][2]=ts[rs][1]; tm[rs][2]=tm[rs][1];
                                ts[rs][1]=v; tm[rs][1]=m;
                            }
                        } else { ts[rs][2]=v; tm[rs][2]=m; }
                    }
                }
            }
        }
        __syncthreads();
    }

    const uint32_t FULL = 0xffffffffu;
    #pragma unroll
    for (int rs = 0; rs < 2; rs++) {
        float m4s[4] = {3.4e38f, 3.4e38f, 3.4e38f, 3.4e38f};
        int   m4i[4] = {0, 0, 0, 0};
        #pragma unroll
        for (int src = 0; src < 4; src++) {
            #pragma unroll
            for (int e = 0; e < 3; e++) {
                float vs = __shfl_sync(FULL, ts[rs][e], (lane & ~3) + src);
                int   vm = __shfl_sync(FULL, tm[rs][e], (lane & ~3) + src);
                if ((lane & 3) == 0) {
                    if (vs < m4s[3]) {
                        if (vs < m4s[1]) {
                            if (vs < m4s[0]) {
                                m4s[3]=m4s[2]; m4i[3]=m4i[2]; m4s[2]=m4s[1]; m4i[2]=m4i[1];
                                m4s[1]=m4s[0]; m4i[1]=m4i[0]; m4s[0]=vs; m4i[0]=vm;
                            } else {
                                m4s[3]=m4s[2]; m4i[3]=m4i[2]; m4s[2]=m4s[1]; m4i[2]=m4i[1];
                                m4s[1]=vs; m4i[1]=vm;
                            }
                        } else {
                            if (vs < m4s[2]) { m4s[3]=m4s[2]; m4i[3]=m4i[2]; m4s[2]=vs; m4i[2]=vm; }
                            else             { m4s[3]=vs; m4i[3]=vm; }
                        }
                    }
                }
            }
        }
        if ((lane & 3) == 0) {
            int bn = bnh * 128 + w * 16 + rs * 8 + (lane >> 2);
            size_t base = ((size_t)bn * Cv + c) * 8 + mh * 4;
            #pragma unroll
            for (int t = 0; t < 4; t++) g_cand[base + t] = mh * 2048 + m4i[t];
        }
    }
}

// ---------------------------------------------------------------------------
__global__ void __launch_bounds__(256) rescore_kernel(const float* __restrict__ cb) {
    int wp   = (blockIdx.x * 256 + threadIdx.x) >> 5;
    int lane = threadIdx.x & 31;
    int bn   = wp >> 8;
    int c    = wp & 255;
    float4 x = *(const float4*)(g_xp + ((size_t)c * BNv + bn) * Ev + lane * 4);
    float best = 3.4e38f; int bm = Mv;
    #pragma unroll
    for (int t = 0; t < 8; t++) {
        int m = g_cand[((size_t)bn * Cv + c) * 8 + t];
        float4 cv = *(const float4*)(cb + ((size_t)c * Mv + m) * Ev + lane * 4);
        float d = x.x * cv.x + x.y * cv.y + x.z * cv.z + x.w * cv.w;
        #pragma unroll
        for (int o = 16; o; o >>= 1) d += __shfl_xor_sync(0xffffffffu, d, o);
        float s = g_esq[(size_t)c * Mv + m] - 2.f * d;
        if (s < best || (s == best && m < bm)) { best = s; bm = m; }
    }
    if (lane == 0) g_idx[(size_t)bn * Cv + c] = bm;
}

// ---------------------------------------------------------------------------
__global__ void __launch_bounds__(256) stage3_kernel(const float* __restrict__ vals,
                                                     float* __restrict__ out) {
    __shared__ float sh[256][Vv];
    const int bn = blockIdx.x;
    const int c  = threadIdx.x;
    int m = g_idx[(size_t)bn * Cv + c];
    const float* vp = vals + ((size_t)c * Mv + m) * Vv;
    #pragma unroll
    for (int v = 0; v < Vv; v++) sh[c][v] = vp[v];
    __syncthreads();
    if (c < Vv) {
        float s = 0.f;
        for (int k = 0; k < 256; k++) s += sh[k][c];
        out[(size_t)bn * Vv + c] = s * (1.f / 256.f);
    }
}

// ---------------------------------------------------------------------------
extern "C" void kernel_launch(void* const* d_in, const int* in_sizes, int n_in,
                              void* d_out, int out_size) {
    const float* emb  = (const float*)d_in[0];
    const float* rp   = (const float*)d_in[1];
    const float* cb   = (const float*)d_in[2];
    const float* vals = (const float*)d_in[3];
    float* out = (float*)d_out;

    cudaFuncSetAttribute(mma_kernel, cudaFuncAttributeMaxDynamicSharedMemorySize, SMEM2);

    prep_kernel<<<(Cv * Mv) / 8, 256>>>(cb);
    stage1_kernel<<<Cv * 2, 256>>>(emb, rp);
    mma_kernel<<<Cv * 4, 256, SMEM2>>>();
    rescore_kernel<<<(BNv * Cv) / 8, 256>>>(cb);
    stage3_kernel<<<BNv, 256>>>(vals, out);
}

// round 15
// speedup vs baseline: 1.4108x; 1.0210x over previous
#include <cuda_runtime.h>
#include <cuda_bf16.h>
#include <cstdint>

// Problem constants
#define BNv 256
#define Dv  2048
#define Cv  256
#define Ev  128
#define Mv  4096
#define Vv  10

#define KEXT 144
#define ROWB (KEXT * 2)
#define SSTR 304

// Scratch
__device__ float g_xp[(size_t)Cv * BNv * Ev];
__device__ float g_esq[(size_t)Cv * Mv];
__device__ int   g_idx[(size_t)BNv * Cv];
__device__ int   g_cand[(size_t)BNv * Cv * 8];
__device__ __align__(16) unsigned char g_cbb[(size_t)Cv * Mv * ROWB];

// ---------------------------------------------------------------------------
__device__ __forceinline__ uint32_t smem_u32(const void* p) {
    uint32_t a;
    asm("{ .reg .u64 t; cvta.to.shared.u64 t, %1; cvt.u32.u64 %0, t; }" : "=r"(a) : "l"(p));
    return a;
}
__device__ __forceinline__ void cp16(uint32_t dst, const void* src) {
    asm volatile("cp.async.cg.shared.global [%0], [%1], 16;" :: "r"(dst), "l"(src) : "memory");
}
__device__ __forceinline__ void cp_commit() { asm volatile("cp.async.commit_group;" ::: "memory"); }
__device__ __forceinline__ void cp_wait0()  { asm volatile("cp.async.wait_group 0;"  ::: "memory"); }

__device__ __forceinline__ void ldm4(uint32_t& r0, uint32_t& r1, uint32_t& r2, uint32_t& r3, uint32_t a) {
    asm volatile("ldmatrix.sync.aligned.m8n8.x4.shared.b16 {%0,%1,%2,%3}, [%4];"
                 : "=r"(r0), "=r"(r1), "=r"(r2), "=r"(r3) : "r"(a));
}
__device__ __forceinline__ void mma16816(float* c, const uint32_t* a, uint32_t b0, uint32_t b1) {
    asm volatile("mma.sync.aligned.m16n8k16.row.col.f32.bf16.bf16.f32 "
                 "{%0,%1,%2,%3}, {%4,%5,%6,%7}, {%8,%9}, {%0,%1,%2,%3};"
                 : "+f"(c[0]), "+f"(c[1]), "+f"(c[2]), "+f"(c[3])
                 : "r"(a[0]), "r"(a[1]), "r"(a[2]), "r"(a[3]), "r"(b0), "r"(b1));
}
__device__ __forceinline__ uint32_t pack_bf2(float x, float y) {
    return ((uint32_t)__bfloat16_as_ushort(__float2bfloat16(y)) << 16) |
           __bfloat16_as_ushort(__float2bfloat16(x));
}
// packed fp32x2 helpers (Blackwell FFMA2) -- each lane is an exact fp32 RN fma
__device__ __forceinline__ unsigned long long pack_ff(float x, float y) {
    unsigned long long r;
    asm("mov.b64 %0, {%1, %2};" : "=l"(r) : "f"(x), "f"(y));
    return r;
}
__device__ __forceinline__ void unpack_ff(unsigned long long d, float& x, float& y) {
    asm("mov.b64 {%0, %1}, %2;" : "=f"(x), "=f"(y) : "l"(d));
}
__device__ __forceinline__ void ffma2(unsigned long long& d, unsigned long long a, unsigned long long b) {
    asm("fma.rn.f32x2 %0, %1, %2, %0;" : "+l"(d) : "l"(a), "l"(b));
}

// ---------------------------------------------------------------------------
// prep: codebook -> bf16 ext rows [cb | esq_hi | esq_lo | zeros], + g_esq
// (VERBATIM R9/R14)
// ---------------------------------------------------------------------------
__global__ void __launch_bounds__(256) prep_kernel(const float* __restrict__ cb) {
    int row  = (blockIdx.x * 256 + threadIdx.x) >> 5;
    int lane = threadIdx.x & 31;
    float4 v = *(const float4*)(cb + (size_t)row * Ev + lane * 4);
    float s = v.x * v.x + v.y * v.y + v.z * v.z + v.w * v.w;
    #pragma unroll
    for (int o = 16; o; o >>= 1) s += __shfl_xor_sync(0xffffffffu, s, o);

    unsigned char* dst = g_cbb + (size_t)row * ROWB;
    uint2 u;
    u.x = pack_bf2(v.x, v.y);
    u.y = pack_bf2(v.z, v.w);
    *(uint2*)(dst + lane * 8) = u;

    if (lane == 0) {
        g_esq[row] = s;
        __nv_bfloat16 hi = __float2bfloat16(s);
        float lo = s - __bfloat162float(hi);
        *(uint32_t*)(dst + 256) =
            ((uint32_t)__bfloat16_as_ushort(__float2bfloat16(lo)) << 16) |
            __bfloat16_as_ushort(hi);
    } else if (lane < 8) {
        *(uint32_t*)(dst + 256 + lane * 4) = 0u;
    }
}

// ---------------------------------------------------------------------------
// stage1: xp = emb . rp via packed FFMA2.
// Numerics: per element acc = fma(a_k,b_k,acc), k ascending -> xp bitwise
// identical to R9/R14. vs R14: block tile 64bn x 128e (grid 1024 = 6.92
// CTAs/SM -> ~1% load imbalance instead of 15.6% at grid 512).
// 8 warps: warp tile 32bn x 32e (wbn = wid&1, we = wid>>1).
// Thread tile: 4 bn-pairs x 4 e. acc2[4][4].
// ---------------------------------------------------------------------------
__global__ void __launch_bounds__(256, 2) stage1_kernel(const float* __restrict__ emb,
                                                        const float* __restrict__ rp) {
    __shared__ __align__(16) float As[16][66];    // [k][bn] 64+2
    __shared__ __align__(16) float Bs[16][132];   // [k][e]

    const int t = threadIdx.x;
    const int c = blockIdx.x >> 2;
    const int bn0g = (blockIdx.x & 3) * 64;
    const float* __restrict__ bb = rp + (size_t)c * (Dv * Ev);

    const int wid  = t >> 5, lane = t & 31;
    const int wbn  = wid & 1;          // bn-warp (0..1) * 32
    const int we   = wid >> 1;         // e-warp  (0..3) * 32
    const int g    = lane >> 3;        // bn subgroup *8
    const int el   = lane & 7;         // e lane

    // LDG mappings
    const int arow = t >> 2;           // 0..63
    const int akq  = (t & 3) * 4;      // k offset 0,4,8,12
    const int bk   = t >> 4;           // 0..15
    const int be   = (t & 15) * 8;     // e offset

    const float* __restrict__ aptr = emb + (size_t)(bn0g + arow) * Dv + akq;
    const float* __restrict__ bptr = bb + (size_t)bk * Ev + be;

    float4 av  = *(const float4*)(aptr);
    float4 bv0 = *(const float4*)(bptr);
    float4 bv1 = *(const float4*)(bptr + 4);

    unsigned long long acc2[4][4];
    #pragma unroll
    for (int p = 0; p < 4; p++)
        #pragma unroll
        for (int j = 0; j < 4; j++) acc2[p][j] = 0ull;

    const int abase = wbn * 32 + g * 8;
    const int ebase = we * 32 + el;

    for (int k0 = 0; k0 < Dv; k0 += 16) {
        __syncthreads();   // previous tile fully consumed
        As[akq + 0][arow] = av.x;
        As[akq + 1][arow] = av.y;
        As[akq + 2][arow] = av.z;
        As[akq + 3][arow] = av.w;
        *(float4*)&Bs[bk][be]     = bv0;
        *(float4*)&Bs[bk][be + 4] = bv1;
        __syncthreads();

        if (k0 + 16 < Dv) {
            av  = *(const float4*)(aptr + (k0 + 16));
            bv0 = *(const float4*)(bptr + (size_t)(k0 + 16) * Ev);
            bv1 = *(const float4*)(bptr + (size_t)(k0 + 16) * Ev + 4);
        }

        #pragma unroll
        for (int kk = 0; kk < 16; kk++) {
            unsigned long long a2[4], b2[4];
            #pragma unroll
            for (int p = 0; p < 4; p++)
                a2[p] = *(const unsigned long long*)&As[kk][abase + 2 * p];
            #pragma unroll
            for (int j = 0; j < 4; j++) {
                float bf = Bs[kk][ebase + 8 * j];
                b2[j] = pack_ff(bf, bf);
            }
            #pragma unroll
            for (int p = 0; p < 4; p++)
                #pragma unroll
                for (int j = 0; j < 4; j++)
                    ffma2(acc2[p][j], a2[p], b2[j]);
        }
    }

    // store xp: pair (bn, bn+1) same e
    #pragma unroll
    for (int p = 0; p < 4; p++) {
        const int bn = bn0g + abase + 2 * p;
        #pragma unroll
        for (int j = 0; j < 4; j++) {
            float v0, v1;
            unpack_ff(acc2[p][j], v0, v1);
            const size_t base = ((size_t)c * BNv + bn) * Ev + ebase + 8 * j;
            g_xp[base]      = v0;
            g_xp[base + Ev] = v1;
        }
    }
}

// ---------------------------------------------------------------------------
// mma stage (stage2): bf16 candidates (VERBATIM R14 -- occupancy-2 split).
// ---------------------------------------------------------------------------
#define XS_BYTES (128 * SSTR)            // 38912
#define CB_BYTES (64 * SSTR)             // 19456
#define SMEM2 (XS_BYTES + 2 * CB_BYTES)  // 77824

__global__ void __launch_bounds__(256, 2) mma_kernel() {
    extern __shared__ __align__(16) unsigned char sm[];
    const uint32_t smb = smem_u32(sm);
    const int tid  = threadIdx.x;
    const int w    = tid >> 5;
    const int lane = tid & 31;
    const int c   = blockIdx.x >> 2;
    const int mh  = (blockIdx.x >> 1) & 1;
    const int bnh = blockIdx.x & 1;

    // X convert: 128 rows, each thread does half a row (16 quads)
    {
        const int r  = tid >> 1;
        const int q0 = (tid & 1) * 16;
        const float* xr = g_xp + ((size_t)(c * BNv + bnh * 128 + r)) * Ev;
        unsigned char* xd = sm + (size_t)r * SSTR;
        #pragma unroll 8
        for (int q = q0; q < q0 + 16; q++) {
            float4 v = *(const float4*)(xr + q * 4);
            uint2 u;
            u.x = pack_bf2(-2.f * v.x, -2.f * v.y);
            u.y = pack_bf2(-2.f * v.z, -2.f * v.w);
            *(uint2*)(xd + q * 8) = u;
        }
        if ((tid & 1) == 0) {
            *(uint32_t*)(xd + 256) = 0x3F803F80u;
            #pragma unroll
            for (int z = 0; z < 7; z++) *(uint32_t*)(xd + 260 + z * 4) = 0u;
        }
    }

    const size_t cb_base = (size_t)(c * Mv + mh * 2048) * ROWB;
    const uint32_t cbs = smb + XS_BYTES;
    {
        #pragma unroll
        for (int s = 0; s < 5; s++) {
            int idx = tid + s * 256;
            if (idx < 1152) {
                int row = idx / 18, ch = idx % 18;
                cp16(cbs + row * SSTR + ch * 16, g_cbb + cb_base + (size_t)row * ROWB + ch * 16);
            }
        }
        cp_commit();
    }

    const int grp = lane >> 3;
    const uint32_t a_off = ((grp & 1) * 8 + (lane & 7)) * SSTR + (grp >> 1) * 16;
    const uint32_t b_off = ((grp >> 1) * 8 + (lane & 7)) * SSTR + (grp & 1) * 16;
    const uint32_t xw = smb + (w * 16) * SSTR + a_off;

    float ts[2][3];
    int   tm[2][3];
    #pragma unroll
    for (int r = 0; r < 2; r++)
        #pragma unroll
        for (int e = 0; e < 3; e++) { ts[r][e] = 3.4e38f; tm[r][e] = 0; }

    for (int it = 0; it < 32; it++) {
        const int buf = it & 1;
        cp_wait0();
        __syncthreads();
        if (it < 31) {
            const uint32_t dst = cbs + (buf ^ 1) * CB_BYTES;
            const size_t src = cb_base + (size_t)(it + 1) * 64 * ROWB;
            #pragma unroll
            for (int s = 0; s < 5; s++) {
                int idx = tid + s * 256;
                if (idx < 1152) {
                    int row = idx / 18, ch = idx % 18;
                    cp16(dst + row * SSTR + ch * 16, g_cbb + src + (size_t)row * ROWB + ch * 16);
                }
            }
            cp_commit();
        }

        float acc[8][4];
        #pragma unroll
        for (int j = 0; j < 8; j++)
            #pragma unroll
            for (int e = 0; e < 4; e++) acc[j][e] = 0.f;

        const uint32_t cw = cbs + buf * CB_BYTES + b_off;

        #pragma unroll
        for (int ks = 0; ks < 9; ks++) {
            uint32_t A[4], B[8][2];
            ldm4(A[0], A[1], A[2], A[3], xw + ks * 32);
            #pragma unroll
            for (int jj = 0; jj < 4; jj++) {
                uint32_t r0, r1, r2, r3;
                ldm4(r0, r1, r2, r3, cw + jj * 16 * SSTR + ks * 32);
                B[2 * jj][0] = r0; B[2 * jj][1] = r1;
                B[2 * jj + 1][0] = r2; B[2 * jj + 1][1] = r3;
            }
            #pragma unroll
            for (int j = 0; j < 8; j++)
                mma16816(acc[j], A, B[j][0], B[j][1]);
        }

        // epilogue: exact top-3 insertion (R9 semantics)
        const int mb = it * 64 + (lane & 3) * 2;
        #pragma unroll
        for (int j = 0; j < 8; j++) {
            const int m0 = mb + j * 8;
            #pragma unroll
            for (int half = 0; half < 2; half++) {
                const int rs = half;
                #pragma unroll
                for (int e = 0; e < 2; e++) {
                    float v = acc[j][half * 2 + e];
                    int   m = m0 + e;
                    if (v < ts[rs][2]) {
                        if (v < ts[rs][1]) {
                            if (v < ts[rs][0]) {
                                ts[rs][2]=ts[rs][1]; tm[rs][2]=tm[rs][1];
                                ts[rs][1]=ts[rs][0]; tm[rs][1]=tm[rs][0];
                                ts[rs][0]=v; tm[rs][0]=m;
                            } else {
                                ts[rs][2]=ts[rs][1]; tm[rs][2]=tm[rs][1];
                                ts[rs][1]=v; tm[rs][1]=m;
                            }
                        } else { ts[rs][2]=v; tm[rs][2]=m; }
                    }
                }
            }
        }
        __syncthreads();
    }

    const uint32_t FULL = 0xffffffffu;
    #pragma unroll
    for (int rs = 0; rs < 2; rs++) {
        float m4s[4] = {3.4e38f, 3.4e38f, 3.4e38f, 3.4e38f};
        int   m4i[4] = {0, 0, 0, 0};
        #pragma unroll
        for (int src = 0; src < 4; src++) {
            #pragma unroll
            for (int e = 0; e < 3; e++) {
                float vs = __shfl_sync(FULL, ts[rs][e], (lane & ~3) + src);
                int   vm = __shfl_sync(FULL, tm[rs][e], (lane & ~3) + src);
                if ((lane & 3) == 0) {
                    if (vs < m4s[3]) {
                        if (vs < m4s[1]) {
                            if (vs < m4s[0]) {
                                m4s[3]=m4s[2]; m4i[3]=m4i[2]; m4s[2]=m4s[1]; m4i[2]=m4i[1];
                                m4s[1]=m4s[0]; m4i[1]=m4i[0]; m4s[0]=vs; m4i[0]=vm;
                            } else {
                                m4s[3]=m4s[2]; m4i[3]=m4i[2]; m4s[2]=m4s[1]; m4i[2]=m4i[1];
                                m4s[1]=vs; m4i[1]=vm;
                            }
                        } else {
                            if (vs < m4s[2]) { m4s[3]=m4s[2]; m4i[3]=m4i[2]; m4s[2]=vs; m4i[2]=vm; }
                            else             { m4s[3]=vs; m4i[3]=vm; }
                        }
                    }
                }
            }
        }
        if ((lane & 3) == 0) {
            int bn = bnh * 128 + w * 16 + rs * 8 + (lane >> 2);
            size_t base = ((size_t)bn * Cv + c) * 8 + mh * 4;
            #pragma unroll
            for (int t = 0; t < 4; t++) g_cand[base + t] = mh * 2048 + m4i[t];
        }
    }
}

// ---------------------------------------------------------------------------
__global__ void __launch_bounds__(256) rescore_kernel(const float* __restrict__ cb) {
    int wp   = (blockIdx.x * 256 + threadIdx.x) >> 5;
    int lane = threadIdx.x & 31;
    int bn   = wp >> 8;
    int c    = wp & 255;
    float4 x = *(const float4*)(g_xp + ((size_t)c * BNv + bn) * Ev + lane * 4);
    float best = 3.4e38f; int bm = Mv;
    #pragma unroll
    for (int t = 0; t < 8; t++) {
        int m = g_cand[((size_t)bn * Cv + c) * 8 + t];
        float4 cv = *(const float4*)(cb + ((size_t)c * Mv + m) * Ev + lane * 4);
        float d = x.x * cv.x + x.y * cv.y + x.z * cv.z + x.w * cv.w;
        #pragma unroll
        for (int o = 16; o; o >>= 1) d += __shfl_xor_sync(0xffffffffu, d, o);
        float s = g_esq[(size_t)c * Mv + m] - 2.f * d;
        if (s < best || (s == best && m < bm)) { best = s; bm = m; }
    }
    if (lane == 0) g_idx[(size_t)bn * Cv + c] = bm;
}

// ---------------------------------------------------------------------------
__global__ void __launch_bounds__(256) stage3_kernel(const float* __restrict__ vals,
                                                     float* __restrict__ out) {
    __shared__ float sh[256][Vv];
    const int bn = blockIdx.x;
    const int c  = threadIdx.x;
    int m = g_idx[(size_t)bn * Cv + c];
    const float* vp = vals + ((size_t)c * Mv + m) * Vv;
    #pragma unroll
    for (int v = 0; v < Vv; v++) sh[c][v] = vp[v];
    __syncthreads();
    if (c < Vv) {
        float s = 0.f;
        for (int k = 0; k < 256; k++) s += sh[k][c];
        out[(size_t)bn * Vv + c] = s * (1.f / 256.f);
    }
}

// ---------------------------------------------------------------------------
extern "C" void kernel_launch(void* const* d_in, const int* in_sizes, int n_in,
                              void* d_out, int out_size) {
    const float* emb  = (const float*)d_in[0];
    const float* rp   = (const float*)d_in[1];
    const float* cb   = (const float*)d_in[2];
    const float* vals = (const float*)d_in[3];
    float* out = (float*)d_out;

    cudaFuncSetAttribute(mma_kernel, cudaFuncAttributeMaxDynamicSharedMemorySize, SMEM2);

    prep_kernel<<<(Cv * Mv) / 8, 256>>>(cb);
    stage1_kernel<<<Cv * 4, 256>>>(emb, rp);
    mma_kernel<<<Cv * 4, 256, SMEM2>>>();
    rescore_kernel<<<(BNv * Cv) / 8, 256>>>(cb);
    stage3_kernel<<<BNv, 256>>>(vals, out);
}